// round 1
// baseline (speedup 1.0000x reference)
#include <cuda_runtime.h>
#include <math.h>

#define BATCH 8
#define SEQ 256
#define DIM 256
#define HEADS 8
#define DKH 32
#define LAYERS 4
#define VOCAB 2048
#define FFD 1024
#define NTOK (BATCH*SEQ)

// ---------------- scratch (allocation-free: __device__ globals) ----------------
__device__ float g_x [NTOK*DIM];
__device__ float g_xn[NTOK*DIM];
__device__ float g_q [NTOK*DIM];
__device__ float g_k [NTOK*DIM];
__device__ float g_v [NTOK*DIM];
__device__ float g_z [NTOK*DIM];
__device__ float g_ff[NTOK*FFD];

// ---------------- embedding ----------------
__global__ void embed_kernel(const int* __restrict__ tokens, const int* __restrict__ positions,
                             const float* __restrict__ value_tab, const float* __restrict__ coord_tab,
                             const float* __restrict__ pos_tab, float* __restrict__ x)
{
    int n = blockIdx.x, d = threadIdx.x;
    int t = tokens[n], p = positions[n];
    x[(size_t)n*DIM + d] = value_tab[(size_t)t*DIM + d] * 16.0f   // sqrt(256)
                         + coord_tab[(p % 3)*DIM + d]
                         + pos_tab[(p / 3)*DIM + d];
}

// ---------------- layernorm (one block of 256 threads per row) ----------------
__global__ void ln_kernel(const float* __restrict__ x, const float* __restrict__ g,
                          const float* __restrict__ b, float* __restrict__ out)
{
    int row = blockIdx.x;
    int tid = threadIdx.x; // 256 == DIM
    float v = x[(size_t)row*DIM + tid];
    float s = v, sq = v*v;
    #pragma unroll
    for (int o = 16; o; o >>= 1) {
        s  += __shfl_xor_sync(0xffffffffu, s,  o);
        sq += __shfl_xor_sync(0xffffffffu, sq, o);
    }
    __shared__ float rs[8], rq[8];
    __shared__ float s_mean, s_rstd;
    if ((tid & 31) == 0) { rs[tid >> 5] = s; rq[tid >> 5] = sq; }
    __syncthreads();
    if (tid == 0) {
        float S = 0.f, Q = 0.f;
        #pragma unroll
        for (int i = 0; i < 8; i++) { S += rs[i]; Q += rq[i]; }
        float mean = S * (1.0f/DIM);
        float var  = Q * (1.0f/DIM) - mean*mean;
        s_mean = mean;
        s_rstd = rsqrtf(var + 1e-5f);
    }
    __syncthreads();
    out[(size_t)row*DIM + tid] = (v - s_mean) * s_rstd * g[tid] + b[tid];
}

// ---------------- generic tiled SGEMM: C = A[M,K] @ W[K,Nd] (+bias)(+res)(relu) ----------------
// 64x64 tile, K-tile 16, 256 threads, 4x4 microtile per thread.
__global__ void gemm_kernel(const float* __restrict__ A, const float* __restrict__ W,
                            const float* __restrict__ bias, const float* __restrict__ res,
                            float* __restrict__ C, int M, int K, int Nd, int relu)
{
    __shared__ float As[16][64];
    __shared__ float Bs[16][64];
    int tid = threadIdx.x;
    int tx = tid & 15, ty = tid >> 4;
    int row0 = blockIdx.y * 64, col0 = blockIdx.x * 64;
    int aRow = tid >> 2,  aCol = (tid & 3)  << 2;   // A tile 64x16, float4 per thread
    int bRow = tid >> 4,  bCol = (tid & 15) << 2;   // B tile 16x64, float4 per thread

    float acc[4][4];
    #pragma unroll
    for (int i = 0; i < 4; i++)
        #pragma unroll
        for (int j = 0; j < 4; j++) acc[i][j] = 0.f;

    for (int k0 = 0; k0 < K; k0 += 16) {
        float4 a = *(const float4*)&A[(size_t)(row0 + aRow)*K + k0 + aCol];
        As[aCol+0][aRow] = a.x; As[aCol+1][aRow] = a.y;
        As[aCol+2][aRow] = a.z; As[aCol+3][aRow] = a.w;
        *(float4*)&Bs[bRow][bCol] = *(const float4*)&W[(size_t)(k0 + bRow)*Nd + col0 + bCol];
        __syncthreads();
        #pragma unroll
        for (int kk = 0; kk < 16; kk++) {
            float4 ra = *(const float4*)&As[kk][ty << 2];
            float4 rb = *(const float4*)&Bs[kk][tx << 2];
            float ras[4] = {ra.x, ra.y, ra.z, ra.w};
            float rbs[4] = {rb.x, rb.y, rb.z, rb.w};
            #pragma unroll
            for (int i = 0; i < 4; i++)
                #pragma unroll
                for (int j = 0; j < 4; j++)
                    acc[i][j] += ras[i] * rbs[j];
        }
        __syncthreads();
    }

    #pragma unroll
    for (int i = 0; i < 4; i++) {
        int row = row0 + (ty << 2) + i;
        #pragma unroll
        for (int j = 0; j < 4; j++) {
            int col = col0 + (tx << 2) + j;
            float val = acc[i][j];
            if (bias) val += bias[col];
            if (res)  val += res[(size_t)row*Nd + col];
            if (relu) val = fmaxf(val, 0.f);
            C[(size_t)row*Nd + col] = val;
        }
    }
}

// ---------------- causal attention, one (batch, head, q-split) per block ----------------
// 128 threads, each thread owns one query; K/V staged in dynamic smem; online softmax.
// j is warp-uniform at every step -> all smem reads are broadcasts.
__global__ void attn_kernel(const float* __restrict__ q, const float* __restrict__ k,
                            const float* __restrict__ v, float* __restrict__ z)
{
    extern __shared__ float4 sh4[];
    float4* Ks = sh4;
    float4* Vs = sh4 + SEQ*(DKH/4);
    int b = blockIdx.x, h = blockIdx.y, s = blockIdx.z;
    int tid = threadIdx.x;           // 128
    int base = b * SEQ;
    int nrows = (s + 1) * 128;       // keys needed by this query split

    for (int i = tid; i < nrows*(DKH/4); i += 128) {
        int row = i >> 3, c = i & 7;
        size_t off = (size_t)(base + row)*DIM + h*DKH + c*4;
        Ks[row*8 + c] = *(const float4*)&k[off];
        Vs[row*8 + c] = *(const float4*)&v[off];
    }
    __syncthreads();

    int i = s*128 + tid;
    const float scale = 0.17677669529663687f;   // 1/sqrt(32)
    float4 qr[8];
    #pragma unroll
    for (int d = 0; d < 8; d++) {
        float4 t = *(const float4*)&q[(size_t)(base + i)*DIM + h*DKH + d*4];
        qr[d].x = t.x*scale; qr[d].y = t.y*scale; qr[d].z = t.z*scale; qr[d].w = t.w*scale;
    }

    float m = -1e30f, l = 0.f;
    float4 acc[8];
    #pragma unroll
    for (int d = 0; d < 8; d++) acc[d] = make_float4(0.f, 0.f, 0.f, 0.f);

    for (int j = 0; j <= i; j++) {
        float s0 = 0.f, s1 = 0.f, s2 = 0.f, s3 = 0.f;
        #pragma unroll
        for (int d = 0; d < 8; d++) {
            float4 kk = Ks[j*8 + d];
            s0 += qr[d].x*kk.x; s1 += qr[d].y*kk.y;
            s2 += qr[d].z*kk.z; s3 += qr[d].w*kk.w;
        }
        float sc = (s0 + s1) + (s2 + s3);
        if (sc > m) {                      // rare rescale path
            float corr = __expf(m - sc);
            l *= corr;
            #pragma unroll
            for (int d = 0; d < 8; d++) {
                acc[d].x *= corr; acc[d].y *= corr; acc[d].z *= corr; acc[d].w *= corr;
            }
            m = sc;
        }
        float p = __expf(sc - m);
        l += p;
        #pragma unroll
        for (int d = 0; d < 8; d++) {
            float4 vv = Vs[j*8 + d];
            acc[d].x += p*vv.x; acc[d].y += p*vv.y;
            acc[d].z += p*vv.z; acc[d].w += p*vv.w;
        }
    }

    float inv = 1.0f / l;
    #pragma unroll
    for (int d = 0; d < 8; d++) {
        float4 o = make_float4(acc[d].x*inv, acc[d].y*inv, acc[d].z*inv, acc[d].w*inv);
        *(float4*)&z[(size_t)(base + i)*DIM + h*DKH + d*4] = o;
    }
}

// ---------------- log_softmax in-place on [NTOK, VOCAB] ----------------
__global__ void logsoftmax_kernel(float* __restrict__ out)
{
    int row = blockIdx.x;
    float* p = out + (size_t)row*VOCAB;
    int tid = threadIdx.x; // 256
    __shared__ float red[8];
    __shared__ float s_m, s_l;

    float m = -1e30f;
    for (int c = tid; c < VOCAB; c += 256) m = fmaxf(m, p[c]);
    #pragma unroll
    for (int o = 16; o; o >>= 1) m = fmaxf(m, __shfl_xor_sync(0xffffffffu, m, o));
    if ((tid & 31) == 0) red[tid >> 5] = m;
    __syncthreads();
    if (tid == 0) {
        float mm = red[0];
        #pragma unroll
        for (int i = 1; i < 8; i++) mm = fmaxf(mm, red[i]);
        s_m = mm;
    }
    __syncthreads();
    m = s_m;

    float s = 0.f;
    for (int c = tid; c < VOCAB; c += 256) s += expf(p[c] - m);
    #pragma unroll
    for (int o = 16; o; o >>= 1) s += __shfl_xor_sync(0xffffffffu, s, o);
    if ((tid & 31) == 0) red[tid >> 5] = s;
    __syncthreads();
    if (tid == 0) {
        float S = 0.f;
        #pragma unroll
        for (int i = 0; i < 8; i++) S += red[i];
        s_l = logf(S);
    }
    __syncthreads();
    float L = s_l;
    for (int c = tid; c < VOCAB; c += 256) p[c] = p[c] - m - L;
}

// ---------------- launcher ----------------
extern "C" void kernel_launch(void* const* d_in, const int* in_sizes, int n_in,
                              void* d_out, int out_size)
{
    const int*   tokens    = (const int*)  d_in[0];
    const int*   positions = (const int*)  d_in[1];
    // d_in[2]=src, d_in[3]=dst: causal-by-construction, not needed
    const float* value_tab = (const float*)d_in[4];
    const float* coord_tab = (const float*)d_in[5];
    const float* pos_tab   = (const float*)d_in[6];
    const float* ln1_g     = (const float*)d_in[7];
    const float* ln1_b     = (const float*)d_in[8];
    const float* Wq        = (const float*)d_in[9];
    const float* Wk        = (const float*)d_in[10];
    const float* Wv        = (const float*)d_in[11];
    const float* Wo        = (const float*)d_in[12];
    const float* ln2_g     = (const float*)d_in[13];
    const float* ln2_b     = (const float*)d_in[14];
    const float* W1        = (const float*)d_in[15];
    const float* b1        = (const float*)d_in[16];
    const float* W2        = (const float*)d_in[17];
    const float* b2        = (const float*)d_in[18];
    const float* lnf_g     = (const float*)d_in[19];
    const float* lnf_b     = (const float*)d_in[20];
    const float* Wgen      = (const float*)d_in[21];
    const float* bgen      = (const float*)d_in[22];
    float* out = (float*)d_out;

    float *x, *xn, *q, *k, *v, *z, *ff;
    cudaGetSymbolAddress((void**)&x,  g_x);
    cudaGetSymbolAddress((void**)&xn, g_xn);
    cudaGetSymbolAddress((void**)&q,  g_q);
    cudaGetSymbolAddress((void**)&k,  g_k);
    cudaGetSymbolAddress((void**)&v,  g_v);
    cudaGetSymbolAddress((void**)&z,  g_z);
    cudaGetSymbolAddress((void**)&ff, g_ff);

    cudaFuncSetAttribute(attn_kernel, cudaFuncAttributeMaxDynamicSharedMemorySize, 65536);

    embed_kernel<<<NTOK, DIM>>>(tokens, positions, value_tab, coord_tab, pos_tab, x);

    dim3 gD(DIM/64,   NTOK/64);   // [2048,256] outputs
    dim3 gF(FFD/64,   NTOK/64);   // [2048,1024]
    dim3 gV(VOCAB/64, NTOK/64);   // [2048,2048]

    for (int i = 0; i < LAYERS; i++) {
        ln_kernel<<<NTOK, DIM>>>(x, ln1_g + i*DIM, ln1_b + i*DIM, xn);
        gemm_kernel<<<gD, 256>>>(xn, Wq + (size_t)i*DIM*DIM, nullptr, nullptr, q, NTOK, DIM, DIM, 0);
        gemm_kernel<<<gD, 256>>>(xn, Wk + (size_t)i*DIM*DIM, nullptr, nullptr, k, NTOK, DIM, DIM, 0);
        gemm_kernel<<<gD, 256>>>(xn, Wv + (size_t)i*DIM*DIM, nullptr, nullptr, v, NTOK, DIM, DIM, 0);
        attn_kernel<<<dim3(BATCH, HEADS, 2), 128, 65536>>>(q, k, v, z);
        gemm_kernel<<<gD, 256>>>(z, Wo + (size_t)i*DIM*DIM, nullptr, x, x, NTOK, DIM, DIM, 0);
        ln_kernel<<<NTOK, DIM>>>(x, ln2_g + i*DIM, ln2_b + i*DIM, xn);
        gemm_kernel<<<gF, 256>>>(xn, W1 + (size_t)i*DIM*FFD, b1 + i*FFD, nullptr, ff, NTOK, DIM, FFD, 1);
        gemm_kernel<<<gD, 256>>>(ff, W2 + (size_t)i*FFD*DIM, b2 + i*DIM, x, x, NTOK, FFD, DIM, 0);
    }

    ln_kernel<<<NTOK, DIM>>>(x, lnf_g, lnf_b, xn);
    gemm_kernel<<<gV, 256>>>(xn, Wgen, bgen, nullptr, out, NTOK, DIM, VOCAB, 0);
    logsoftmax_kernel<<<NTOK, 256>>>(out);
}

// round 2
// speedup vs baseline: 1.9962x; 1.9962x over previous
#include <cuda_runtime.h>
#include <math.h>

#define BATCH 8
#define SEQ 256
#define DIM 256
#define HEADS 8
#define DKH 32
#define LAYERS 4
#define VOCAB 2048
#define FFD 1024
#define NTOK (BATCH*SEQ)

// ---------------- scratch (allocation-free: __device__ globals) ----------------
__device__ float g_x [NTOK*DIM];
__device__ float g_xn[NTOK*DIM];
__device__ float g_q [NTOK*DIM];
__device__ float g_k [NTOK*DIM];
__device__ float g_v [NTOK*DIM];
__device__ float g_z [NTOK*DIM];
__device__ float g_ff[NTOK*FFD];

// ---------------- helpers ----------------
__device__ __forceinline__ unsigned f2tf(float f) {
    unsigned u;
    asm("cvt.rna.tf32.f32 %0, %1;" : "=r"(u) : "f"(f));
    return u;
}

__device__ __forceinline__ void mma_tf32(float c[4],
                                         unsigned a0, unsigned a1, unsigned a2, unsigned a3,
                                         unsigned b0, unsigned b1)
{
    asm volatile(
        "mma.sync.aligned.m16n8k8.row.col.f32.tf32.tf32.f32 "
        "{%0,%1,%2,%3}, {%4,%5,%6,%7}, {%8,%9}, {%0,%1,%2,%3};\n"
        : "+f"(c[0]), "+f"(c[1]), "+f"(c[2]), "+f"(c[3])
        : "r"(a0), "r"(a1), "r"(a2), "r"(a3), "r"(b0), "r"(b1));
}

// ---------------- embedding ----------------
__global__ void embed_kernel(const int* __restrict__ tokens, const int* __restrict__ positions,
                             const float* __restrict__ value_tab, const float* __restrict__ coord_tab,
                             const float* __restrict__ pos_tab, float* __restrict__ x)
{
    int n = blockIdx.x, d = threadIdx.x;
    int t = tokens[n], p = positions[n];
    x[(size_t)n*DIM + d] = value_tab[(size_t)t*DIM + d] * 16.0f
                         + coord_tab[(p % 3)*DIM + d]
                         + pos_tab[(p / 3)*DIM + d];
}

// ---------------- layernorm ----------------
__global__ void ln_kernel(const float* __restrict__ x, const float* __restrict__ g,
                          const float* __restrict__ b, float* __restrict__ out)
{
    int row = blockIdx.x;
    int tid = threadIdx.x; // 256 == DIM
    float v = x[(size_t)row*DIM + tid];
    float s = v, sq = v*v;
    #pragma unroll
    for (int o = 16; o; o >>= 1) {
        s  += __shfl_xor_sync(0xffffffffu, s,  o);
        sq += __shfl_xor_sync(0xffffffffu, sq, o);
    }
    __shared__ float rs[8], rq[8];
    __shared__ float s_mean, s_rstd;
    if ((tid & 31) == 0) { rs[tid >> 5] = s; rq[tid >> 5] = sq; }
    __syncthreads();
    if (tid == 0) {
        float S = 0.f, Q = 0.f;
        #pragma unroll
        for (int i = 0; i < 8; i++) { S += rs[i]; Q += rq[i]; }
        float mean = S * (1.0f/DIM);
        float var  = Q * (1.0f/DIM) - mean*mean;
        s_mean = mean;
        s_rstd = rsqrtf(var + 1e-5f);
    }
    __syncthreads();
    out[(size_t)row*DIM + tid] = (v - s_mean) * s_rstd * g[tid] + b[tid];
}

// ---------------- tf32 tensor-core GEMM ----------------
// C = A[M,K] @ W[K,Nd] (+bias)(+res)(relu)
// 64x64 CTA tile, BK=32, 128 threads = 4 warps, warp tile 32x32 (2x4 m16n8k8).
// blockIdx.z selects among (W0,C0),(W1,C1),(W2,C2) for fused QKV.
#define BM 64
#define BN 64
#define BK 32

__global__ __launch_bounds__(128) void gemm_tf32(
    const float* __restrict__ A,
    const float* __restrict__ Wp0, const float* __restrict__ Wp1, const float* __restrict__ Wp2,
    const float* __restrict__ bias, const float* __restrict__ res,
    float* __restrict__ Cp0, float* __restrict__ Cp1, float* __restrict__ Cp2,
    int M, int K, int Nd, int relu)
{
    const float* W = (blockIdx.z == 0) ? Wp0 : ((blockIdx.z == 1) ? Wp1 : Wp2);
    float*       C = (blockIdx.z == 0) ? Cp0 : ((blockIdx.z == 1) ? Cp1 : Cp2);

    __shared__ unsigned As[2][BM][BK + 4];   // [m][k], pad 4 -> frag loads conflict-free
    __shared__ unsigned Bs[2][BK][BN + 8];   // [k][n], pad 8 -> frag loads conflict-free

    int tid  = threadIdx.x;
    int lane = tid & 31, warp = tid >> 5;
    int wm = (warp & 1) * 32;       // warp row offset in tile
    int wn = (warp >> 1) * 32;      // warp col offset in tile
    int row0 = blockIdx.y * BM, col0 = blockIdx.x * BN;
    int r = lane >> 2, cq = lane & 3;

    float acc[2][4][4];
    #pragma unroll
    for (int mi = 0; mi < 2; mi++)
        #pragma unroll
        for (int ni = 0; ni < 4; ni++)
            #pragma unroll
            for (int j = 0; j < 4; j++) acc[mi][ni][j] = 0.f;

    // per-thread gmem load coordinates
    // A tile 64x32: idx = tid + i*128; arow = idx/8, akc = (idx%8)*4
    // B tile 32x64: idx = tid + i*128; bkr = idx/16, bnc = (idx%16)*4
    int arow = tid >> 3,        akc = (tid & 7) << 2;     // + i*16 rows
    int bkr  = tid >> 4,        bnc = (tid & 15) << 2;    // + i*8 rows

    const int NK = K / BK;

    float4 ar[4], br[4];

    // prologue: load tile 0
    #pragma unroll
    for (int i = 0; i < 4; i++) {
        ar[i] = *(const float4*)&A[(size_t)(row0 + arow + i*16)*K + akc];
        br[i] = *(const float4*)&W[(size_t)(bkr + i*8)*Nd + col0 + bnc];
    }
    #pragma unroll
    for (int i = 0; i < 4; i++) {
        uint4 ua = make_uint4(f2tf(ar[i].x), f2tf(ar[i].y), f2tf(ar[i].z), f2tf(ar[i].w));
        *(uint4*)&As[0][arow + i*16][akc] = ua;
        uint4 ub = make_uint4(f2tf(br[i].x), f2tf(br[i].y), f2tf(br[i].z), f2tf(br[i].w));
        *(uint4*)&Bs[0][bkr + i*8][bnc] = ub;
    }
    __syncthreads();

    for (int ki = 0; ki < NK; ki++) {
        int buf = ki & 1;
        // prefetch next tile into registers
        if (ki + 1 < NK) {
            int k0 = (ki + 1) * BK;
            #pragma unroll
            for (int i = 0; i < 4; i++) {
                ar[i] = *(const float4*)&A[(size_t)(row0 + arow + i*16)*K + k0 + akc];
                br[i] = *(const float4*)&W[(size_t)(k0 + bkr + i*8)*Nd + col0 + bnc];
            }
        }
        // compute current buffer
        #pragma unroll
        for (int kk = 0; kk < 4; kk++) {
            int kb = kk * 8;
            unsigned af[2][4], bf[4][2];
            #pragma unroll
            for (int mi = 0; mi < 2; mi++) {
                int m = wm + mi*16 + r;
                af[mi][0] = As[buf][m    ][kb + cq];
                af[mi][1] = As[buf][m + 8][kb + cq];
                af[mi][2] = As[buf][m    ][kb + cq + 4];
                af[mi][3] = As[buf][m + 8][kb + cq + 4];
            }
            #pragma unroll
            for (int ni = 0; ni < 4; ni++) {
                int n = wn + ni*8 + r;
                bf[ni][0] = Bs[buf][kb + cq    ][n];
                bf[ni][1] = Bs[buf][kb + cq + 4][n];
            }
            #pragma unroll
            for (int mi = 0; mi < 2; mi++)
                #pragma unroll
                for (int ni = 0; ni < 4; ni++)
                    mma_tf32(acc[mi][ni], af[mi][0], af[mi][1], af[mi][2], af[mi][3],
                             bf[ni][0], bf[ni][1]);
        }
        // store prefetched tile into other buffer
        if (ki + 1 < NK) {
            int nb = buf ^ 1;
            #pragma unroll
            for (int i = 0; i < 4; i++) {
                uint4 ua = make_uint4(f2tf(ar[i].x), f2tf(ar[i].y), f2tf(ar[i].z), f2tf(ar[i].w));
                *(uint4*)&As[nb][arow + i*16][akc] = ua;
                uint4 ub = make_uint4(f2tf(br[i].x), f2tf(br[i].y), f2tf(br[i].z), f2tf(br[i].w));
                *(uint4*)&Bs[nb][bkr + i*8][bnc] = ub;
            }
            __syncthreads();
        }
    }

    // epilogue: write C with optional bias/residual/relu (float2 stores)
    #pragma unroll
    for (int mi = 0; mi < 2; mi++) {
        #pragma unroll
        for (int ni = 0; ni < 4; ni++) {
            int row = row0 + wm + mi*16 + r;
            int col = col0 + wn + ni*8 + cq*2;
            #pragma unroll
            for (int half = 0; half < 2; half++) {
                int rr = row + half*8;
                float v0 = acc[mi][ni][half*2 + 0];
                float v1 = acc[mi][ni][half*2 + 1];
                if (bias) { v0 += bias[col]; v1 += bias[col + 1]; }
                if (res)  {
                    float2 rv = *(const float2*)&res[(size_t)rr*Nd + col];
                    v0 += rv.x; v1 += rv.y;
                }
                if (relu) { v0 = fmaxf(v0, 0.f); v1 = fmaxf(v1, 0.f); }
                float2 o = make_float2(v0, v1);
                *(float2*)&C[(size_t)rr*Nd + col] = o;
            }
        }
    }
}

// ---------------- causal attention ----------------
__global__ void attn_kernel(const float* __restrict__ q, const float* __restrict__ k,
                            const float* __restrict__ v, float* __restrict__ z)
{
    extern __shared__ float4 sh4[];
    float4* Ks = sh4;
    float4* Vs = sh4 + SEQ*(DKH/4);
    int b = blockIdx.x, h = blockIdx.y, s = blockIdx.z;
    int tid = threadIdx.x;           // 128
    int base = b * SEQ;
    int nrows = (s + 1) * 128;

    for (int i = tid; i < nrows*(DKH/4); i += 128) {
        int row = i >> 3, c = i & 7;
        size_t off = (size_t)(base + row)*DIM + h*DKH + c*4;
        Ks[row*8 + c] = *(const float4*)&k[off];
        Vs[row*8 + c] = *(const float4*)&v[off];
    }
    __syncthreads();

    int i = s*128 + tid;
    const float scale = 0.17677669529663687f;
    float4 qr[8];
    #pragma unroll
    for (int d = 0; d < 8; d++) {
        float4 t = *(const float4*)&q[(size_t)(base + i)*DIM + h*DKH + d*4];
        qr[d].x = t.x*scale; qr[d].y = t.y*scale; qr[d].z = t.z*scale; qr[d].w = t.w*scale;
    }

    float m = -1e30f, l = 0.f;
    float4 acc[8];
    #pragma unroll
    for (int d = 0; d < 8; d++) acc[d] = make_float4(0.f, 0.f, 0.f, 0.f);

    for (int j = 0; j <= i; j++) {
        float s0 = 0.f, s1 = 0.f, s2 = 0.f, s3 = 0.f;
        #pragma unroll
        for (int d = 0; d < 8; d++) {
            float4 kk = Ks[j*8 + d];
            s0 += qr[d].x*kk.x; s1 += qr[d].y*kk.y;
            s2 += qr[d].z*kk.z; s3 += qr[d].w*kk.w;
        }
        float sc = (s0 + s1) + (s2 + s3);
        if (sc > m) {
            float corr = __expf(m - sc);
            l *= corr;
            #pragma unroll
            for (int d = 0; d < 8; d++) {
                acc[d].x *= corr; acc[d].y *= corr; acc[d].z *= corr; acc[d].w *= corr;
            }
            m = sc;
        }
        float p = __expf(sc - m);
        l += p;
        #pragma unroll
        for (int d = 0; d < 8; d++) {
            float4 vv = Vs[j*8 + d];
            acc[d].x += p*vv.x; acc[d].y += p*vv.y;
            acc[d].z += p*vv.z; acc[d].w += p*vv.w;
        }
    }

    float inv = 1.0f / l;
    #pragma unroll
    for (int d = 0; d < 8; d++) {
        float4 o = make_float4(acc[d].x*inv, acc[d].y*inv, acc[d].z*inv, acc[d].w*inv);
        *(float4*)&z[(size_t)(base + i)*DIM + h*DKH + d*4] = o;
    }
}

// ---------------- log_softmax in-place on [NTOK, VOCAB] ----------------
__global__ void logsoftmax_kernel(float* __restrict__ out)
{
    int row = blockIdx.x;
    float* p = out + (size_t)row*VOCAB;
    int tid = threadIdx.x; // 256
    __shared__ float red[8];
    __shared__ float s_m, s_l;

    float m = -1e30f;
    for (int c = tid; c < VOCAB; c += 256) m = fmaxf(m, p[c]);
    #pragma unroll
    for (int o = 16; o; o >>= 1) m = fmaxf(m, __shfl_xor_sync(0xffffffffu, m, o));
    if ((tid & 31) == 0) red[tid >> 5] = m;
    __syncthreads();
    if (tid == 0) {
        float mm = red[0];
        #pragma unroll
        for (int i = 1; i < 8; i++) mm = fmaxf(mm, red[i]);
        s_m = mm;
    }
    __syncthreads();
    m = s_m;

    float s = 0.f;
    for (int c = tid; c < VOCAB; c += 256) s += expf(p[c] - m);
    #pragma unroll
    for (int o = 16; o; o >>= 1) s += __shfl_xor_sync(0xffffffffu, s, o);
    if ((tid & 31) == 0) red[tid >> 5] = s;
    __syncthreads();
    if (tid == 0) {
        float S = 0.f;
        #pragma unroll
        for (int i = 0; i < 8; i++) S += red[i];
        s_l = logf(S);
    }
    __syncthreads();
    float L = s_l;
    for (int c = tid; c < VOCAB; c += 256) p[c] = p[c] - m - L;
}

// ---------------- launcher ----------------
extern "C" void kernel_launch(void* const* d_in, const int* in_sizes, int n_in,
                              void* d_out, int out_size)
{
    const int*   tokens    = (const int*)  d_in[0];
    const int*   positions = (const int*)  d_in[1];
    const float* value_tab = (const float*)d_in[4];
    const float* coord_tab = (const float*)d_in[5];
    const float* pos_tab   = (const float*)d_in[6];
    const float* ln1_g     = (const float*)d_in[7];
    const float* ln1_b     = (const float*)d_in[8];
    const float* Wq        = (const float*)d_in[9];
    const float* Wk        = (const float*)d_in[10];
    const float* Wv        = (const float*)d_in[11];
    const float* Wo        = (const float*)d_in[12];
    const float* ln2_g     = (const float*)d_in[13];
    const float* ln2_b     = (const float*)d_in[14];
    const float* W1        = (const float*)d_in[15];
    const float* b1        = (const float*)d_in[16];
    const float* W2        = (const float*)d_in[17];
    const float* b2        = (const float*)d_in[18];
    const float* lnf_g     = (const float*)d_in[19];
    const float* lnf_b     = (const float*)d_in[20];
    const float* Wgen      = (const float*)d_in[21];
    const float* bgen      = (const float*)d_in[22];
    float* out = (float*)d_out;

    float *x, *xn, *q, *k, *v, *z, *ff;
    cudaGetSymbolAddress((void**)&x,  g_x);
    cudaGetSymbolAddress((void**)&xn, g_xn);
    cudaGetSymbolAddress((void**)&q,  g_q);
    cudaGetSymbolAddress((void**)&k,  g_k);
    cudaGetSymbolAddress((void**)&v,  g_v);
    cudaGetSymbolAddress((void**)&z,  g_z);
    cudaGetSymbolAddress((void**)&ff, g_ff);

    cudaFuncSetAttribute(attn_kernel, cudaFuncAttributeMaxDynamicSharedMemorySize, 65536);

    embed_kernel<<<NTOK, DIM>>>(tokens, positions, value_tab, coord_tab, pos_tab, x);

    dim3 gD(DIM/BN,   NTOK/BM, 1);    // [2048,256] outputs
    dim3 gQKV(DIM/BN, NTOK/BM, 3);    // fused QKV
    dim3 gF(FFD/BN,   NTOK/BM, 1);    // [2048,1024]
    dim3 gV(VOCAB/BN, NTOK/BM, 1);    // [2048,2048]

    for (int i = 0; i < LAYERS; i++) {
        ln_kernel<<<NTOK, DIM>>>(x, ln1_g + i*DIM, ln1_b + i*DIM, xn);
        gemm_tf32<<<gQKV, 128>>>(xn,
                                 Wq + (size_t)i*DIM*DIM, Wk + (size_t)i*DIM*DIM, Wv + (size_t)i*DIM*DIM,
                                 nullptr, nullptr, q, k, v, NTOK, DIM, DIM, 0);
        attn_kernel<<<dim3(BATCH, HEADS, 2), 128, 65536>>>(q, k, v, z);
        gemm_tf32<<<gD, 128>>>(z, Wo + (size_t)i*DIM*DIM, nullptr, nullptr,
                               nullptr, x, x, nullptr, nullptr, NTOK, DIM, DIM, 0);
        ln_kernel<<<NTOK, DIM>>>(x, ln2_g + i*DIM, ln2_b + i*DIM, xn);
        gemm_tf32<<<gF, 128>>>(xn, W1 + (size_t)i*DIM*FFD, nullptr, nullptr,
                               b1 + i*FFD, nullptr, ff, nullptr, nullptr, NTOK, DIM, FFD, 1);
        gemm_tf32<<<gD, 128>>>(ff, W2 + (size_t)i*FFD*DIM, nullptr, nullptr,
                               b2 + i*DIM, x, x, nullptr, nullptr, NTOK, FFD, DIM, 0);
    }

    ln_kernel<<<NTOK, DIM>>>(x, lnf_g, lnf_b, xn);
    gemm_tf32<<<gV, 128>>>(xn, Wgen, nullptr, nullptr,
                           bgen, nullptr, out, nullptr, nullptr, NTOK, DIM, VOCAB, 0);
    logsoftmax_kernel<<<NTOK, 256>>>(out);
}

// round 3
// speedup vs baseline: 2.2120x; 1.1081x over previous
#include <cuda_runtime.h>
#include <math.h>

#define BATCH 8
#define SEQ 256
#define DIM 256
#define HEADS 8
#define DKH 32
#define LAYERS 4
#define VOCAB 2048
#define FFD 1024
#define NTOK (BATCH*SEQ)

// ---------------- scratch (allocation-free: __device__ globals) ----------------
__device__ float g_x [NTOK*DIM];
__device__ float g_xn[NTOK*DIM];
__device__ float g_q [NTOK*DIM];
__device__ float g_k [NTOK*DIM];
__device__ float g_v [NTOK*DIM];
__device__ float g_z [NTOK*DIM];
__device__ float g_ff[NTOK*FFD];

// ---------------- helpers ----------------
__device__ __forceinline__ unsigned f2tf(float f) {
    unsigned u;
    asm("cvt.rna.tf32.f32 %0, %1;" : "=r"(u) : "f"(f));
    return u;
}

__device__ __forceinline__ void mma_tf32(float c[4],
                                         unsigned a0, unsigned a1, unsigned a2, unsigned a3,
                                         unsigned b0, unsigned b1)
{
    asm volatile(
        "mma.sync.aligned.m16n8k8.row.col.f32.tf32.tf32.f32 "
        "{%0,%1,%2,%3}, {%4,%5,%6,%7}, {%8,%9}, {%0,%1,%2,%3};\n"
        : "+f"(c[0]), "+f"(c[1]), "+f"(c[2]), "+f"(c[3])
        : "r"(a0), "r"(a1), "r"(a2), "r"(a3), "r"(b0), "r"(b1));
}

// ---------------- embedding ----------------
__global__ void embed_kernel(const int* __restrict__ tokens, const int* __restrict__ positions,
                             const float* __restrict__ value_tab, const float* __restrict__ coord_tab,
                             const float* __restrict__ pos_tab, float* __restrict__ x)
{
    int n = blockIdx.x, d = threadIdx.x;
    int t = tokens[n], p = positions[n];
    x[(size_t)n*DIM + d] = value_tab[(size_t)t*DIM + d] * 16.0f
                         + coord_tab[(p % 3)*DIM + d]
                         + pos_tab[(p / 3)*DIM + d];
}

// ---------------- layernorm ----------------
__global__ void ln_kernel(const float* __restrict__ x, const float* __restrict__ g,
                          const float* __restrict__ b, float* __restrict__ out)
{
    int row = blockIdx.x;
    int tid = threadIdx.x; // 256 == DIM
    float v = x[(size_t)row*DIM + tid];
    float s = v, sq = v*v;
    #pragma unroll
    for (int o = 16; o; o >>= 1) {
        s  += __shfl_xor_sync(0xffffffffu, s,  o);
        sq += __shfl_xor_sync(0xffffffffu, sq, o);
    }
    __shared__ float rs[8], rq[8];
    __shared__ float s_mean, s_rstd;
    if ((tid & 31) == 0) { rs[tid >> 5] = s; rq[tid >> 5] = sq; }
    __syncthreads();
    if (tid == 0) {
        float S = 0.f, Q = 0.f;
        #pragma unroll
        for (int i = 0; i < 8; i++) { S += rs[i]; Q += rq[i]; }
        float mean = S * (1.0f/DIM);
        float var  = Q * (1.0f/DIM) - mean*mean;
        s_mean = mean;
        s_rstd = rsqrtf(var + 1e-5f);
    }
    __syncthreads();
    out[(size_t)row*DIM + tid] = (v - s_mean) * s_rstd * g[tid] + b[tid];
}

// ---------------- tf32 tensor-core GEMM ----------------
#define BM 64
#define BN 64
#define BK 32

__global__ __launch_bounds__(128) void gemm_tf32(
    const float* __restrict__ A,
    const float* __restrict__ Wp0, const float* __restrict__ Wp1, const float* __restrict__ Wp2,
    const float* __restrict__ bias, const float* __restrict__ res,
    float* __restrict__ Cp0, float* __restrict__ Cp1, float* __restrict__ Cp2,
    int M, int K, int Nd, int relu)
{
    const float* W = (blockIdx.z == 0) ? Wp0 : ((blockIdx.z == 1) ? Wp1 : Wp2);
    float*       C = (blockIdx.z == 0) ? Cp0 : ((blockIdx.z == 1) ? Cp1 : Cp2);

    __shared__ unsigned As[2][BM][BK + 4];
    __shared__ unsigned Bs[2][BK][BN + 8];

    int tid  = threadIdx.x;
    int lane = tid & 31, warp = tid >> 5;
    int wm = (warp & 1) * 32;
    int wn = (warp >> 1) * 32;
    int row0 = blockIdx.y * BM, col0 = blockIdx.x * BN;
    int r = lane >> 2, cq = lane & 3;

    float acc[2][4][4];
    #pragma unroll
    for (int mi = 0; mi < 2; mi++)
        #pragma unroll
        for (int ni = 0; ni < 4; ni++)
            #pragma unroll
            for (int j = 0; j < 4; j++) acc[mi][ni][j] = 0.f;

    int arow = tid >> 3,        akc = (tid & 7) << 2;
    int bkr  = tid >> 4,        bnc = (tid & 15) << 2;

    const int NK = K / BK;
    float4 ar[4], br[4];

    #pragma unroll
    for (int i = 0; i < 4; i++) {
        ar[i] = *(const float4*)&A[(size_t)(row0 + arow + i*16)*K + akc];
        br[i] = *(const float4*)&W[(size_t)(bkr + i*8)*Nd + col0 + bnc];
    }
    #pragma unroll
    for (int i = 0; i < 4; i++) {
        uint4 ua = make_uint4(f2tf(ar[i].x), f2tf(ar[i].y), f2tf(ar[i].z), f2tf(ar[i].w));
        *(uint4*)&As[0][arow + i*16][akc] = ua;
        uint4 ub = make_uint4(f2tf(br[i].x), f2tf(br[i].y), f2tf(br[i].z), f2tf(br[i].w));
        *(uint4*)&Bs[0][bkr + i*8][bnc] = ub;
    }
    __syncthreads();

    for (int ki = 0; ki < NK; ki++) {
        int buf = ki & 1;
        if (ki + 1 < NK) {
            int k0 = (ki + 1) * BK;
            #pragma unroll
            for (int i = 0; i < 4; i++) {
                ar[i] = *(const float4*)&A[(size_t)(row0 + arow + i*16)*K + k0 + akc];
                br[i] = *(const float4*)&W[(size_t)(k0 + bkr + i*8)*Nd + col0 + bnc];
            }
        }
        #pragma unroll
        for (int kk = 0; kk < 4; kk++) {
            int kb = kk * 8;
            unsigned af[2][4], bf[4][2];
            #pragma unroll
            for (int mi = 0; mi < 2; mi++) {
                int m = wm + mi*16 + r;
                af[mi][0] = As[buf][m    ][kb + cq];
                af[mi][1] = As[buf][m + 8][kb + cq];
                af[mi][2] = As[buf][m    ][kb + cq + 4];
                af[mi][3] = As[buf][m + 8][kb + cq + 4];
            }
            #pragma unroll
            for (int ni = 0; ni < 4; ni++) {
                int n = wn + ni*8 + r;
                bf[ni][0] = Bs[buf][kb + cq    ][n];
                bf[ni][1] = Bs[buf][kb + cq + 4][n];
            }
            #pragma unroll
            for (int mi = 0; mi < 2; mi++)
                #pragma unroll
                for (int ni = 0; ni < 4; ni++)
                    mma_tf32(acc[mi][ni], af[mi][0], af[mi][1], af[mi][2], af[mi][3],
                             bf[ni][0], bf[ni][1]);
        }
        if (ki + 1 < NK) {
            int nb = buf ^ 1;
            #pragma unroll
            for (int i = 0; i < 4; i++) {
                uint4 ua = make_uint4(f2tf(ar[i].x), f2tf(ar[i].y), f2tf(ar[i].z), f2tf(ar[i].w));
                *(uint4*)&As[nb][arow + i*16][akc] = ua;
                uint4 ub = make_uint4(f2tf(br[i].x), f2tf(br[i].y), f2tf(br[i].z), f2tf(br[i].w));
                *(uint4*)&Bs[nb][bkr + i*8][bnc] = ub;
            }
            __syncthreads();
        }
    }

    #pragma unroll
    for (int mi = 0; mi < 2; mi++) {
        #pragma unroll
        for (int ni = 0; ni < 4; ni++) {
            int row = row0 + wm + mi*16 + r;
            int col = col0 + wn + ni*8 + cq*2;
            #pragma unroll
            for (int half = 0; half < 2; half++) {
                int rr = row + half*8;
                float v0 = acc[mi][ni][half*2 + 0];
                float v1 = acc[mi][ni][half*2 + 1];
                if (bias) { v0 += bias[col]; v1 += bias[col + 1]; }
                if (res)  {
                    float2 rv = *(const float2*)&res[(size_t)rr*Nd + col];
                    v0 += rv.x; v1 += rv.y;
                }
                if (relu) { v0 = fmaxf(v0, 0.f); v1 = fmaxf(v1, 0.f); }
                float2 o = make_float2(v0, v1);
                *(float2*)&C[(size_t)rr*Nd + col] = o;
            }
        }
    }
}

// ---------------- causal attention: warp-per-query-pair, lane-parallel keys ----------------
// grid (B, H, 8): each block handles 32 queries; 128 threads = 4 warps,
// each warp handles 8 queries as 4 pairs. Lanes split the key loop.
// Scores are O(1) (LN-bounded) -> direct exp (softmax is shift-invariant; no max pass).
#define KST 9   // float4 stride per K/V row (padded: conflict-free per 8-lane phase)

__global__ __launch_bounds__(128) void attn_kernel(
    const float* __restrict__ q, const float* __restrict__ k,
    const float* __restrict__ v, float* __restrict__ z)
{
    extern __shared__ float4 sh4[];
    float4* Ks = sh4;                // [SEQ][KST]
    float4* Vs = sh4 + SEQ*KST;
    int b = blockIdx.x, h = blockIdx.y, s = blockIdx.z;
    int tid = threadIdx.x;           // 128
    int lane = tid & 31, warp = tid >> 5;
    int base = b * SEQ;
    int nrows = (s + 1) * 32;

    for (int i = tid; i < nrows*8; i += 128) {
        int row = i >> 3, c = i & 7;
        size_t off = (size_t)(base + row)*DIM + h*DKH + c*4;
        Ks[row*KST + c] = *(const float4*)&k[off];
        Vs[row*KST + c] = *(const float4*)&v[off];
    }
    __syncthreads();

    const float scale = 0.17677669529663687f;   // 1/sqrt(32)

    #pragma unroll 1
    for (int pp = 0; pp < 4; pp++) {
        int i0 = s*32 + warp*8 + pp*2;
        int i1 = i0 + 1;

        float4 q0[8], q1[8];
        #pragma unroll
        for (int d = 0; d < 8; d++) {
            float4 t0 = *(const float4*)&q[(size_t)(base + i0)*DIM + h*DKH + d*4];
            float4 t1 = *(const float4*)&q[(size_t)(base + i1)*DIM + h*DKH + d*4];
            q0[d].x = t0.x*scale; q0[d].y = t0.y*scale; q0[d].z = t0.z*scale; q0[d].w = t0.w*scale;
            q1[d].x = t1.x*scale; q1[d].y = t1.y*scale; q1[d].z = t1.z*scale; q1[d].w = t1.w*scale;
        }

        float l0 = 0.f, l1 = 0.f;
        float4 a0[8], a1[8];
        #pragma unroll
        for (int d = 0; d < 8; d++) {
            a0[d] = make_float4(0.f,0.f,0.f,0.f);
            a1[d] = make_float4(0.f,0.f,0.f,0.f);
        }

        for (int j = lane; j <= i1; j += 32) {
            const float4* kp = &Ks[j*KST];
            float s0 = 0.f, s1 = 0.f;
            #pragma unroll
            for (int d = 0; d < 8; d++) {
                float4 kk = kp[d];
                s0 += q0[d].x*kk.x + q0[d].y*kk.y + q0[d].z*kk.z + q0[d].w*kk.w;
                s1 += q1[d].x*kk.x + q1[d].y*kk.y + q1[d].z*kk.z + q1[d].w*kk.w;
            }
            float p0 = (j <= i0) ? __expf(s0) : 0.f;
            float p1 = __expf(s1);
            l0 += p0; l1 += p1;
            const float4* vp = &Vs[j*KST];
            #pragma unroll
            for (int d = 0; d < 8; d++) {
                float4 vv = vp[d];
                a0[d].x += p0*vv.x; a0[d].y += p0*vv.y; a0[d].z += p0*vv.z; a0[d].w += p0*vv.w;
                a1[d].x += p1*vv.x; a1[d].y += p1*vv.y; a1[d].z += p1*vv.z; a1[d].w += p1*vv.w;
            }
        }

        // butterfly sum across lanes
        #pragma unroll
        for (int off = 16; off; off >>= 1) {
            l0 += __shfl_xor_sync(0xffffffffu, l0, off);
            l1 += __shfl_xor_sync(0xffffffffu, l1, off);
            #pragma unroll
            for (int d = 0; d < 8; d++) {
                a0[d].x += __shfl_xor_sync(0xffffffffu, a0[d].x, off);
                a0[d].y += __shfl_xor_sync(0xffffffffu, a0[d].y, off);
                a0[d].z += __shfl_xor_sync(0xffffffffu, a0[d].z, off);
                a0[d].w += __shfl_xor_sync(0xffffffffu, a0[d].w, off);
                a1[d].x += __shfl_xor_sync(0xffffffffu, a1[d].x, off);
                a1[d].y += __shfl_xor_sync(0xffffffffu, a1[d].y, off);
                a1[d].z += __shfl_xor_sync(0xffffffffu, a1[d].z, off);
                a1[d].w += __shfl_xor_sync(0xffffffffu, a1[d].w, off);
            }
        }

        if (lane == 0) {
            float inv0 = 1.0f / l0, inv1 = 1.0f / l1;
            #pragma unroll
            for (int d = 0; d < 8; d++) {
                float4 o0 = make_float4(a0[d].x*inv0, a0[d].y*inv0, a0[d].z*inv0, a0[d].w*inv0);
                float4 o1 = make_float4(a1[d].x*inv1, a1[d].y*inv1, a1[d].z*inv1, a1[d].w*inv1);
                *(float4*)&z[(size_t)(base + i0)*DIM + h*DKH + d*4] = o0;
                *(float4*)&z[(size_t)(base + i1)*DIM + h*DKH + d*4] = o1;
            }
        }
    }
}

// ---------------- log_softmax in-place on [NTOK, VOCAB] ----------------
__global__ void logsoftmax_kernel(float* __restrict__ out)
{
    int row = blockIdx.x;
    float* p = out + (size_t)row*VOCAB;
    int tid = threadIdx.x; // 256
    __shared__ float red[8];
    __shared__ float s_m, s_l;

    float m = -1e30f;
    for (int c = tid; c < VOCAB; c += 256) m = fmaxf(m, p[c]);
    #pragma unroll
    for (int o = 16; o; o >>= 1) m = fmaxf(m, __shfl_xor_sync(0xffffffffu, m, o));
    if ((tid & 31) == 0) red[tid >> 5] = m;
    __syncthreads();
    if (tid == 0) {
        float mm = red[0];
        #pragma unroll
        for (int i = 1; i < 8; i++) mm = fmaxf(mm, red[i]);
        s_m = mm;
    }
    __syncthreads();
    m = s_m;

    float s = 0.f;
    for (int c = tid; c < VOCAB; c += 256) s += expf(p[c] - m);
    #pragma unroll
    for (int o = 16; o; o >>= 1) s += __shfl_xor_sync(0xffffffffu, s, o);
    if ((tid & 31) == 0) red[tid >> 5] = s;
    __syncthreads();
    if (tid == 0) {
        float S = 0.f;
        #pragma unroll
        for (int i = 0; i < 8; i++) S += red[i];
        s_l = logf(S);
    }
    __syncthreads();
    float L = s_l;
    for (int c = tid; c < VOCAB; c += 256) p[c] = p[c] - m - L;
}

// ---------------- launcher ----------------
extern "C" void kernel_launch(void* const* d_in, const int* in_sizes, int n_in,
                              void* d_out, int out_size)
{
    const int*   tokens    = (const int*)  d_in[0];
    const int*   positions = (const int*)  d_in[1];
    const float* value_tab = (const float*)d_in[4];
    const float* coord_tab = (const float*)d_in[5];
    const float* pos_tab   = (const float*)d_in[6];
    const float* ln1_g     = (const float*)d_in[7];
    const float* ln1_b     = (const float*)d_in[8];
    const float* Wq        = (const float*)d_in[9];
    const float* Wk        = (const float*)d_in[10];
    const float* Wv        = (const float*)d_in[11];
    const float* Wo        = (const float*)d_in[12];
    const float* ln2_g     = (const float*)d_in[13];
    const float* ln2_b     = (const float*)d_in[14];
    const float* W1        = (const float*)d_in[15];
    const float* b1        = (const float*)d_in[16];
    const float* W2        = (const float*)d_in[17];
    const float* b2        = (const float*)d_in[18];
    const float* lnf_g     = (const float*)d_in[19];
    const float* lnf_b     = (const float*)d_in[20];
    const float* Wgen      = (const float*)d_in[21];
    const float* bgen      = (const float*)d_in[22];
    float* out = (float*)d_out;

    float *x, *xn, *q, *k, *v, *z, *ff;
    cudaGetSymbolAddress((void**)&x,  g_x);
    cudaGetSymbolAddress((void**)&xn, g_xn);
    cudaGetSymbolAddress((void**)&q,  g_q);
    cudaGetSymbolAddress((void**)&k,  g_k);
    cudaGetSymbolAddress((void**)&v,  g_v);
    cudaGetSymbolAddress((void**)&z,  g_z);
    cudaGetSymbolAddress((void**)&ff, g_ff);

    const int ATTN_SMEM = 2 * SEQ * KST * 16;   // 73728 bytes
    cudaFuncSetAttribute(attn_kernel, cudaFuncAttributeMaxDynamicSharedMemorySize, ATTN_SMEM);

    embed_kernel<<<NTOK, DIM>>>(tokens, positions, value_tab, coord_tab, pos_tab, x);

    dim3 gD(DIM/BN,   NTOK/BM, 1);
    dim3 gQKV(DIM/BN, NTOK/BM, 3);
    dim3 gF(FFD/BN,   NTOK/BM, 1);
    dim3 gV(VOCAB/BN, NTOK/BM, 1);

    for (int i = 0; i < LAYERS; i++) {
        ln_kernel<<<NTOK, DIM>>>(x, ln1_g + i*DIM, ln1_b + i*DIM, xn);
        gemm_tf32<<<gQKV, 128>>>(xn,
                                 Wq + (size_t)i*DIM*DIM, Wk + (size_t)i*DIM*DIM, Wv + (size_t)i*DIM*DIM,
                                 nullptr, nullptr, q, k, v, NTOK, DIM, DIM, 0);
        attn_kernel<<<dim3(BATCH, HEADS, 8), 128, ATTN_SMEM>>>(q, k, v, z);
        gemm_tf32<<<gD, 128>>>(z, Wo + (size_t)i*DIM*DIM, nullptr, nullptr,
                               nullptr, x, x, nullptr, nullptr, NTOK, DIM, DIM, 0);
        ln_kernel<<<NTOK, DIM>>>(x, ln2_g + i*DIM, ln2_b + i*DIM, xn);
        gemm_tf32<<<gF, 128>>>(xn, W1 + (size_t)i*DIM*FFD, nullptr, nullptr,
                               b1 + i*FFD, nullptr, ff, nullptr, nullptr, NTOK, DIM, FFD, 1);
        gemm_tf32<<<gD, 128>>>(ff, W2 + (size_t)i*FFD*DIM, nullptr, nullptr,
                               b2 + i*DIM, x, x, nullptr, nullptr, NTOK, FFD, DIM, 0);
    }

    ln_kernel<<<NTOK, DIM>>>(x, lnf_g, lnf_b, xn);
    gemm_tf32<<<gV, 128>>>(xn, Wgen, nullptr, nullptr,
                           bgen, nullptr, out, nullptr, nullptr, NTOK, DIM, VOCAB, 0);
    logsoftmax_kernel<<<NTOK, 256>>>(out);
}

// round 4
// speedup vs baseline: 2.7074x; 1.2240x over previous
#include <cuda_runtime.h>
#include <math.h>

#define BATCH 8
#define SEQ 256
#define DIM 256
#define HEADS 8
#define DKH 32
#define LAYERS 4
#define VOCAB 2048
#define FFD 1024
#define NTOK (BATCH*SEQ)

// ---------------- scratch (allocation-free: __device__ globals) ----------------
__device__ float g_x [NTOK*DIM];
__device__ float g_xn[NTOK*DIM];
__device__ float g_q [NTOK*DIM];
__device__ float g_k [NTOK*DIM];
__device__ float g_v [NTOK*DIM];
__device__ float g_z [NTOK*DIM];
__device__ float g_ff[NTOK*FFD];

// ---------------- helpers ----------------
__device__ __forceinline__ unsigned f2tf(float f) {
    unsigned u;
    asm("cvt.rna.tf32.f32 %0, %1;" : "=r"(u) : "f"(f));
    return u;
}

__device__ __forceinline__ void mma_tf32(float c[4],
                                         unsigned a0, unsigned a1, unsigned a2, unsigned a3,
                                         unsigned b0, unsigned b1)
{
    asm volatile(
        "mma.sync.aligned.m16n8k8.row.col.f32.tf32.tf32.f32 "
        "{%0,%1,%2,%3}, {%4,%5,%6,%7}, {%8,%9}, {%0,%1,%2,%3};\n"
        : "+f"(c[0]), "+f"(c[1]), "+f"(c[2]), "+f"(c[3])
        : "r"(a0), "r"(a1), "r"(a2), "r"(a3), "r"(b0), "r"(b1));
}

// ---------------- embedding ----------------
__global__ void embed_kernel(const int* __restrict__ tokens, const int* __restrict__ positions,
                             const float* __restrict__ value_tab, const float* __restrict__ coord_tab,
                             const float* __restrict__ pos_tab, float* __restrict__ x)
{
    int n = blockIdx.x, d = threadIdx.x;
    int t = tokens[n], p = positions[n];
    x[(size_t)n*DIM + d] = value_tab[(size_t)t*DIM + d] * 16.0f
                         + coord_tab[(p % 3)*DIM + d]
                         + pos_tab[(p / 3)*DIM + d];
}

// ---------------- layernorm ----------------
__global__ void ln_kernel(const float* __restrict__ x, const float* __restrict__ g,
                          const float* __restrict__ b, float* __restrict__ out)
{
    int row = blockIdx.x;
    int tid = threadIdx.x; // 256 == DIM
    float v = x[(size_t)row*DIM + tid];
    float s = v, sq = v*v;
    #pragma unroll
    for (int o = 16; o; o >>= 1) {
        s  += __shfl_xor_sync(0xffffffffu, s,  o);
        sq += __shfl_xor_sync(0xffffffffu, sq, o);
    }
    __shared__ float rs[8], rq[8];
    __shared__ float s_mean, s_rstd;
    if ((tid & 31) == 0) { rs[tid >> 5] = s; rq[tid >> 5] = sq; }
    __syncthreads();
    if (tid == 0) {
        float S = 0.f, Q = 0.f;
        #pragma unroll
        for (int i = 0; i < 8; i++) { S += rs[i]; Q += rq[i]; }
        float mean = S * (1.0f/DIM);
        float var  = Q * (1.0f/DIM) - mean*mean;
        s_mean = mean;
        s_rstd = rsqrtf(var + 1e-5f);
    }
    __syncthreads();
    out[(size_t)row*DIM + tid] = (v - s_mean) * s_rstd * g[tid] + b[tid];
}

// ---------------- tf32 tensor-core GEMM ----------------
#define BM 64
#define BN 64
#define BK 32

__global__ __launch_bounds__(128) void gemm_tf32(
    const float* __restrict__ A,
    const float* __restrict__ Wp0, const float* __restrict__ Wp1, const float* __restrict__ Wp2,
    const float* __restrict__ bias, const float* __restrict__ res,
    float* __restrict__ Cp0, float* __restrict__ Cp1, float* __restrict__ Cp2,
    int M, int K, int Nd, int relu)
{
    const float* W = (blockIdx.z == 0) ? Wp0 : ((blockIdx.z == 1) ? Wp1 : Wp2);
    float*       C = (blockIdx.z == 0) ? Cp0 : ((blockIdx.z == 1) ? Cp1 : Cp2);

    __shared__ unsigned As[2][BM][BK + 4];
    __shared__ unsigned Bs[2][BK][BN + 8];

    int tid  = threadIdx.x;
    int lane = tid & 31, warp = tid >> 5;
    int wm = (warp & 1) * 32;
    int wn = (warp >> 1) * 32;
    int row0 = blockIdx.y * BM, col0 = blockIdx.x * BN;
    int r = lane >> 2, cq = lane & 3;

    float acc[2][4][4];
    #pragma unroll
    for (int mi = 0; mi < 2; mi++)
        #pragma unroll
        for (int ni = 0; ni < 4; ni++)
            #pragma unroll
            for (int j = 0; j < 4; j++) acc[mi][ni][j] = 0.f;

    int arow = tid >> 3,        akc = (tid & 7) << 2;
    int bkr  = tid >> 4,        bnc = (tid & 15) << 2;

    const int NK = K / BK;
    float4 ar[4], br[4];

    #pragma unroll
    for (int i = 0; i < 4; i++) {
        ar[i] = *(const float4*)&A[(size_t)(row0 + arow + i*16)*K + akc];
        br[i] = *(const float4*)&W[(size_t)(bkr + i*8)*Nd + col0 + bnc];
    }
    #pragma unroll
    for (int i = 0; i < 4; i++) {
        uint4 ua = make_uint4(f2tf(ar[i].x), f2tf(ar[i].y), f2tf(ar[i].z), f2tf(ar[i].w));
        *(uint4*)&As[0][arow + i*16][akc] = ua;
        uint4 ub = make_uint4(f2tf(br[i].x), f2tf(br[i].y), f2tf(br[i].z), f2tf(br[i].w));
        *(uint4*)&Bs[0][bkr + i*8][bnc] = ub;
    }
    __syncthreads();

    for (int ki = 0; ki < NK; ki++) {
        int buf = ki & 1;
        if (ki + 1 < NK) {
            int k0 = (ki + 1) * BK;
            #pragma unroll
            for (int i = 0; i < 4; i++) {
                ar[i] = *(const float4*)&A[(size_t)(row0 + arow + i*16)*K + k0 + akc];
                br[i] = *(const float4*)&W[(size_t)(k0 + bkr + i*8)*Nd + col0 + bnc];
            }
        }
        #pragma unroll
        for (int kk = 0; kk < 4; kk++) {
            int kb = kk * 8;
            unsigned af[2][4], bf[4][2];
            #pragma unroll
            for (int mi = 0; mi < 2; mi++) {
                int m = wm + mi*16 + r;
                af[mi][0] = As[buf][m    ][kb + cq];
                af[mi][1] = As[buf][m + 8][kb + cq];
                af[mi][2] = As[buf][m    ][kb + cq + 4];
                af[mi][3] = As[buf][m + 8][kb + cq + 4];
            }
            #pragma unroll
            for (int ni = 0; ni < 4; ni++) {
                int n = wn + ni*8 + r;
                bf[ni][0] = Bs[buf][kb + cq    ][n];
                bf[ni][1] = Bs[buf][kb + cq + 4][n];
            }
            #pragma unroll
            for (int mi = 0; mi < 2; mi++)
                #pragma unroll
                for (int ni = 0; ni < 4; ni++)
                    mma_tf32(acc[mi][ni], af[mi][0], af[mi][1], af[mi][2], af[mi][3],
                             bf[ni][0], bf[ni][1]);
        }
        if (ki + 1 < NK) {
            int nb = buf ^ 1;
            #pragma unroll
            for (int i = 0; i < 4; i++) {
                uint4 ua = make_uint4(f2tf(ar[i].x), f2tf(ar[i].y), f2tf(ar[i].z), f2tf(ar[i].w));
                *(uint4*)&As[nb][arow + i*16][akc] = ua;
                uint4 ub = make_uint4(f2tf(br[i].x), f2tf(br[i].y), f2tf(br[i].z), f2tf(br[i].w));
                *(uint4*)&Bs[nb][bkr + i*8][bnc] = ub;
            }
            __syncthreads();
        }
    }

    #pragma unroll
    for (int mi = 0; mi < 2; mi++) {
        #pragma unroll
        for (int ni = 0; ni < 4; ni++) {
            int row = row0 + wm + mi*16 + r;
            int col = col0 + wn + ni*8 + cq*2;
            #pragma unroll
            for (int half = 0; half < 2; half++) {
                int rr = row + half*8;
                float v0 = acc[mi][ni][half*2 + 0];
                float v1 = acc[mi][ni][half*2 + 1];
                if (bias) { v0 += bias[col]; v1 += bias[col + 1]; }
                if (res)  {
                    float2 rv = *(const float2*)&res[(size_t)rr*Nd + col];
                    v0 += rv.x; v1 += rv.y;
                }
                if (relu) { v0 = fmaxf(v0, 0.f); v1 = fmaxf(v1, 0.f); }
                float2 o = make_float2(v0, v1);
                *(float2*)&C[(size_t)rr*Nd + col] = o;
            }
        }
    }
}

// ---------------- MMA flash attention (tf32, no-max softmax) ----------------
// grid (B, H, 2): block covers 128 query rows with 8 warps (m16 slab each).
// Loop over 32-key tiles: S = Q K^T (MMA), p = exp(S) masked causal, round p to
// tf32 (so l = sum(p) matches PV numerics), O += P V (MMA, P via per-warp smem).
#define KVP 36   // padded 32-bit stride per K/V/P row (conflict-free frag reads)

__global__ __launch_bounds__(256) void attn_kernel(
    const float* __restrict__ q, const float* __restrict__ k,
    const float* __restrict__ v, float* __restrict__ z)
{
    extern __shared__ unsigned sh[];
    unsigned* Ks = sh;                   // [256][KVP]
    unsigned* Vs = sh + 256*KVP;         // [256][KVP]
    unsigned* Ps = sh + 2*256*KVP;       // [8][16][KVP]

    int b = blockIdx.x, h = blockIdx.y, half = blockIdx.z;
    int tid = threadIdx.x, lane = tid & 31, warp = tid >> 5;
    int base = b * SEQ;
    int rows = (half + 1) * 128;

    const float scale = 0.17677669529663687f;   // 1/sqrt(32)

    // stage K/V (tf32-rounded) into smem
    for (int idx = tid; idx < rows*8; idx += 256) {
        int row = idx >> 3, c = (idx & 7) * 4;
        size_t off = (size_t)(base + row)*DIM + h*DKH + c;
        float4 kk = *(const float4*)&k[off];
        float4 vv = *(const float4*)&v[off];
        *(uint4*)&Ks[row*KVP + c] = make_uint4(f2tf(kk.x), f2tf(kk.y), f2tf(kk.z), f2tf(kk.w));
        *(uint4*)&Vs[row*KVP + c] = make_uint4(f2tf(vv.x), f2tf(vv.y), f2tf(vv.z), f2tf(vv.w));
    }
    __syncthreads();

    int r = lane >> 2, cq = lane & 3;
    int q0 = half*128 + warp*16;           // this warp's first query row
    unsigned* Pw = Ps + warp*16*KVP;

    // Q A-fragments (scaled, tf32)
    unsigned qa[4][4];
    #pragma unroll
    for (int ks = 0; ks < 4; ks++) {
        int c0 = ks*8 + cq;
        qa[ks][0] = f2tf(q[(size_t)(base + q0 + r    )*DIM + h*DKH + c0    ] * scale);
        qa[ks][1] = f2tf(q[(size_t)(base + q0 + 8 + r)*DIM + h*DKH + c0    ] * scale);
        qa[ks][2] = f2tf(q[(size_t)(base + q0 + r    )*DIM + h*DKH + c0 + 4] * scale);
        qa[ks][3] = f2tf(q[(size_t)(base + q0 + 8 + r)*DIM + h*DKH + c0 + 4] * scale);
    }

    float oacc[4][4];
    #pragma unroll
    for (int ni = 0; ni < 4; ni++)
        #pragma unroll
        for (int j = 0; j < 4; j++) oacc[ni][j] = 0.f;
    float lsum0 = 0.f, lsum1 = 0.f;

    int ntiles = ((q0 + 15) >> 5) + 1;
    int row0 = q0 + r, row1 = q0 + 8 + r;

    for (int t = 0; t < ntiles; t++) {
        int j0 = t * 32;

        // S = Q K^T for this 16x32 tile
        float s[4][4];
        #pragma unroll
        for (int ni = 0; ni < 4; ni++)
            #pragma unroll
            for (int j = 0; j < 4; j++) s[ni][j] = 0.f;
        #pragma unroll
        for (int ks = 0; ks < 4; ks++) {
            unsigned bf[4][2];
            #pragma unroll
            for (int ni = 0; ni < 4; ni++) {
                int krow = (j0 + ni*8 + r) * KVP + ks*8 + cq;
                bf[ni][0] = Ks[krow];
                bf[ni][1] = Ks[krow + 4];
            }
            #pragma unroll
            for (int ni = 0; ni < 4; ni++)
                mma_tf32(s[ni], qa[ks][0], qa[ks][1], qa[ks][2], qa[ks][3],
                         bf[ni][0], bf[ni][1]);
        }

        // exp + causal mask, round to tf32, accumulate l, spill P to smem
        #pragma unroll
        for (int ni = 0; ni < 4; ni++) {
            int j = j0 + ni*8 + 2*cq;
            float p0 = (j     <= row0) ? __expf(s[ni][0]) : 0.f;
            float p1 = (j + 1 <= row0) ? __expf(s[ni][1]) : 0.f;
            float p2 = (j     <= row1) ? __expf(s[ni][2]) : 0.f;
            float p3 = (j + 1 <= row1) ? __expf(s[ni][3]) : 0.f;
            unsigned u0 = f2tf(p0), u1 = f2tf(p1), u2 = f2tf(p2), u3 = f2tf(p3);
            lsum0 += __uint_as_float(u0) + __uint_as_float(u1);
            lsum1 += __uint_as_float(u2) + __uint_as_float(u3);
            *(uint2*)&Pw[ r      *KVP + ni*8 + 2*cq] = make_uint2(u0, u1);
            *(uint2*)&Pw[(r + 8)*KVP + ni*8 + 2*cq] = make_uint2(u2, u3);
        }
        __syncwarp();

        // O += P V
        #pragma unroll
        for (int ks = 0; ks < 4; ks++) {
            unsigned pa0 = Pw[ r      *KVP + ks*8 + cq    ];
            unsigned pa1 = Pw[(r + 8)*KVP + ks*8 + cq    ];
            unsigned pa2 = Pw[ r      *KVP + ks*8 + cq + 4];
            unsigned pa3 = Pw[(r + 8)*KVP + ks*8 + cq + 4];
            #pragma unroll
            for (int ni = 0; ni < 4; ni++) {
                unsigned b0 = Vs[(j0 + ks*8 + cq    )*KVP + ni*8 + r];
                unsigned b1 = Vs[(j0 + ks*8 + cq + 4)*KVP + ni*8 + r];
                mma_tf32(oacc[ni], pa0, pa1, pa2, pa3, b0, b1);
            }
        }
        __syncwarp();   // protect Pw before next tile overwrites
    }

    // reduce l over the quad (lanes 4r..4r+3 share row r)
    float l0 = lsum0, l1 = lsum1;
    l0 += __shfl_xor_sync(0xffffffffu, l0, 1);
    l0 += __shfl_xor_sync(0xffffffffu, l0, 2);
    l1 += __shfl_xor_sync(0xffffffffu, l1, 1);
    l1 += __shfl_xor_sync(0xffffffffu, l1, 2);
    float inv0 = 1.0f / l0, inv1 = 1.0f / l1;

    #pragma unroll
    for (int ni = 0; ni < 4; ni++) {
        int col = h*DKH + ni*8 + 2*cq;
        float2 o0 = make_float2(oacc[ni][0]*inv0, oacc[ni][1]*inv0);
        float2 o1 = make_float2(oacc[ni][2]*inv1, oacc[ni][3]*inv1);
        *(float2*)&z[(size_t)(base + q0 + r    )*DIM + col] = o0;
        *(float2*)&z[(size_t)(base + q0 + 8 + r)*DIM + col] = o1;
    }
}

// ---------------- log_softmax in-place on [NTOK, VOCAB] ----------------
__global__ void logsoftmax_kernel(float* __restrict__ out)
{
    int row = blockIdx.x;
    float* p = out + (size_t)row*VOCAB;
    int tid = threadIdx.x; // 256
    __shared__ float red[8];
    __shared__ float s_m, s_l;

    float m = -1e30f;
    for (int c = tid; c < VOCAB; c += 256) m = fmaxf(m, p[c]);
    #pragma unroll
    for (int o = 16; o; o >>= 1) m = fmaxf(m, __shfl_xor_sync(0xffffffffu, m, o));
    if ((tid & 31) == 0) red[tid >> 5] = m;
    __syncthreads();
    if (tid == 0) {
        float mm = red[0];
        #pragma unroll
        for (int i = 1; i < 8; i++) mm = fmaxf(mm, red[i]);
        s_m = mm;
    }
    __syncthreads();
    m = s_m;

    float s = 0.f;
    for (int c = tid; c < VOCAB; c += 256) s += expf(p[c] - m);
    #pragma unroll
    for (int o = 16; o; o >>= 1) s += __shfl_xor_sync(0xffffffffu, s, o);
    if ((tid & 31) == 0) red[tid >> 5] = s;
    __syncthreads();
    if (tid == 0) {
        float S = 0.f;
        #pragma unroll
        for (int i = 0; i < 8; i++) S += red[i];
        s_l = logf(S);
    }
    __syncthreads();
    float L = s_l;
    for (int c = tid; c < VOCAB; c += 256) p[c] = p[c] - m - L;
}

// ---------------- launcher ----------------
extern "C" void kernel_launch(void* const* d_in, const int* in_sizes, int n_in,
                              void* d_out, int out_size)
{
    const int*   tokens    = (const int*)  d_in[0];
    const int*   positions = (const int*)  d_in[1];
    const float* value_tab = (const float*)d_in[4];
    const float* coord_tab = (const float*)d_in[5];
    const float* pos_tab   = (const float*)d_in[6];
    const float* ln1_g     = (const float*)d_in[7];
    const float* ln1_b     = (const float*)d_in[8];
    const float* Wq        = (const float*)d_in[9];
    const float* Wk        = (const float*)d_in[10];
    const float* Wv        = (const float*)d_in[11];
    const float* Wo        = (const float*)d_in[12];
    const float* ln2_g     = (const float*)d_in[13];
    const float* ln2_b     = (const float*)d_in[14];
    const float* W1        = (const float*)d_in[15];
    const float* b1        = (const float*)d_in[16];
    const float* W2        = (const float*)d_in[17];
    const float* b2        = (const float*)d_in[18];
    const float* lnf_g     = (const float*)d_in[19];
    const float* lnf_b     = (const float*)d_in[20];
    const float* Wgen      = (const float*)d_in[21];
    const float* bgen      = (const float*)d_in[22];
    float* out = (float*)d_out;

    float *x, *xn, *q, *k, *v, *z, *ff;
    cudaGetSymbolAddress((void**)&x,  g_x);
    cudaGetSymbolAddress((void**)&xn, g_xn);
    cudaGetSymbolAddress((void**)&q,  g_q);
    cudaGetSymbolAddress((void**)&k,  g_k);
    cudaGetSymbolAddress((void**)&v,  g_v);
    cudaGetSymbolAddress((void**)&z,  g_z);
    cudaGetSymbolAddress((void**)&ff, g_ff);

    const int ATTN_SMEM = (2*256*KVP + 8*16*KVP) * 4;   // 92160 bytes
    cudaFuncSetAttribute(attn_kernel, cudaFuncAttributeMaxDynamicSharedMemorySize, ATTN_SMEM);

    embed_kernel<<<NTOK, DIM>>>(tokens, positions, value_tab, coord_tab, pos_tab, x);

    dim3 gD(DIM/BN,   NTOK/BM, 1);
    dim3 gQKV(DIM/BN, NTOK/BM, 3);
    dim3 gF(FFD/BN,   NTOK/BM, 1);
    dim3 gV(VOCAB/BN, NTOK/BM, 1);

    for (int i = 0; i < LAYERS; i++) {
        ln_kernel<<<NTOK, DIM>>>(x, ln1_g + i*DIM, ln1_b + i*DIM, xn);
        gemm_tf32<<<gQKV, 128>>>(xn,
                                 Wq + (size_t)i*DIM*DIM, Wk + (size_t)i*DIM*DIM, Wv + (size_t)i*DIM*DIM,
                                 nullptr, nullptr, q, k, v, NTOK, DIM, DIM, 0);
        attn_kernel<<<dim3(BATCH, HEADS, 2), 256, ATTN_SMEM>>>(q, k, v, z);
        gemm_tf32<<<gD, 128>>>(z, Wo + (size_t)i*DIM*DIM, nullptr, nullptr,
                               nullptr, x, x, nullptr, nullptr, NTOK, DIM, DIM, 0);
        ln_kernel<<<NTOK, DIM>>>(x, ln2_g + i*DIM, ln2_b + i*DIM, xn);
        gemm_tf32<<<gF, 128>>>(xn, W1 + (size_t)i*DIM*FFD, nullptr, nullptr,
                               b1 + i*FFD, nullptr, ff, nullptr, nullptr, NTOK, DIM, FFD, 1);
        gemm_tf32<<<gD, 128>>>(ff, W2 + (size_t)i*FFD*DIM, nullptr, nullptr,
                               b2 + i*DIM, x, x, nullptr, nullptr, NTOK, FFD, DIM, 0);
    }

    ln_kernel<<<NTOK, DIM>>>(x, lnf_g, lnf_b, xn);
    gemm_tf32<<<gV, 128>>>(xn, Wgen, nullptr, nullptr,
                           bgen, nullptr, out, nullptr, nullptr, NTOK, DIM, VOCAB, 0);
    logsoftmax_kernel<<<NTOK, 256>>>(out);
}

// round 5
// speedup vs baseline: 3.1403x; 1.1599x over previous
#include <cuda_runtime.h>
#include <math.h>

#define BATCH 8
#define SEQ 256
#define DIM 256
#define HEADS 8
#define DKH 32
#define LAYERS 4
#define VOCAB 2048
#define FFD 1024
#define NTOK (BATCH*SEQ)

// ---------------- scratch (allocation-free: __device__ globals) ----------------
__device__ float g_x [NTOK*DIM];
__device__ float g_xn[NTOK*DIM];
__device__ float g_q [NTOK*DIM];
__device__ float g_k [NTOK*DIM];
__device__ float g_v [NTOK*DIM];
__device__ float g_z [NTOK*DIM];
__device__ float g_ff[NTOK*FFD];

// ---------------- helpers ----------------
__device__ __forceinline__ unsigned f2tf(float f) {
    unsigned u;
    asm("cvt.rna.tf32.f32 %0, %1;" : "=r"(u) : "f"(f));
    return u;
}

__device__ __forceinline__ unsigned pack_bf16(float lo, float hi) {
    unsigned u;
    asm("cvt.rn.bf16x2.f32 %0, %1, %2;" : "=r"(u) : "f"(hi), "f"(lo));
    return u;
}

__device__ __forceinline__ void mma_tf32(float c[4],
                                         unsigned a0, unsigned a1, unsigned a2, unsigned a3,
                                         unsigned b0, unsigned b1)
{
    asm volatile(
        "mma.sync.aligned.m16n8k8.row.col.f32.tf32.tf32.f32 "
        "{%0,%1,%2,%3}, {%4,%5,%6,%7}, {%8,%9}, {%0,%1,%2,%3};\n"
        : "+f"(c[0]), "+f"(c[1]), "+f"(c[2]), "+f"(c[3])
        : "r"(a0), "r"(a1), "r"(a2), "r"(a3), "r"(b0), "r"(b1));
}

__device__ __forceinline__ void mma_bf16(float c[4],
                                         unsigned a0, unsigned a1, unsigned a2, unsigned a3,
                                         unsigned b0, unsigned b1)
{
    asm volatile(
        "mma.sync.aligned.m16n8k16.row.col.f32.bf16.bf16.f32 "
        "{%0,%1,%2,%3}, {%4,%5,%6,%7}, {%8,%9}, {%0,%1,%2,%3};\n"
        : "+f"(c[0]), "+f"(c[1]), "+f"(c[2]), "+f"(c[3])
        : "r"(a0), "r"(a1), "r"(a2), "r"(a3), "r"(b0), "r"(b1));
}

// ---------------- embedding ----------------
__global__ void embed_kernel(const int* __restrict__ tokens, const int* __restrict__ positions,
                             const float* __restrict__ value_tab, const float* __restrict__ coord_tab,
                             const float* __restrict__ pos_tab, float* __restrict__ x)
{
    int n = blockIdx.x, d = threadIdx.x;
    int t = tokens[n], p = positions[n];
    x[(size_t)n*DIM + d] = value_tab[(size_t)t*DIM + d] * 16.0f
                         + coord_tab[(p % 3)*DIM + d]
                         + pos_tab[(p / 3)*DIM + d];
}

// ---------------- layernorm ----------------
__global__ void ln_kernel(const float* __restrict__ x, const float* __restrict__ g,
                          const float* __restrict__ b, float* __restrict__ out)
{
    int row = blockIdx.x;
    int tid = threadIdx.x; // 256 == DIM
    float v = x[(size_t)row*DIM + tid];
    float s = v, sq = v*v;
    #pragma unroll
    for (int o = 16; o; o >>= 1) {
        s  += __shfl_xor_sync(0xffffffffu, s,  o);
        sq += __shfl_xor_sync(0xffffffffu, sq, o);
    }
    __shared__ float rs[8], rq[8];
    __shared__ float s_mean, s_rstd;
    if ((tid & 31) == 0) { rs[tid >> 5] = s; rq[tid >> 5] = sq; }
    __syncthreads();
    if (tid == 0) {
        float S = 0.f, Q = 0.f;
        #pragma unroll
        for (int i = 0; i < 8; i++) { S += rs[i]; Q += rq[i]; }
        float mean = S * (1.0f/DIM);
        float var  = Q * (1.0f/DIM) - mean*mean;
        s_mean = mean;
        s_rstd = rsqrtf(var + 1e-5f);
    }
    __syncthreads();
    out[(size_t)row*DIM + tid] = (v - s_mean) * s_rstd * g[tid] + b[tid];
}

// ---------------- bf16 tensor-core GEMM ----------------
// C = A[M,K] @ W[K,Nd] (+bias)(+res)(relu); fp32 accumulate.
// 64x64 CTA tile, BK=32, 128 threads = 4 warps, warp tile 32x32 (2x4 m16n8k16).
// Smem holds bf16x2 pairs along K. blockIdx.z selects (W,C) for fused QKV.
#define BM 64
#define BN 64
#define BK 32

__global__ __launch_bounds__(128) void gemm_bf16(
    const float* __restrict__ A,
    const float* __restrict__ Wp0, const float* __restrict__ Wp1, const float* __restrict__ Wp2,
    const float* __restrict__ bias, const float* __restrict__ res,
    float* __restrict__ Cp0, float* __restrict__ Cp1, float* __restrict__ Cp2,
    int M, int K, int Nd, int relu)
{
    const float* W = (blockIdx.z == 0) ? Wp0 : ((blockIdx.z == 1) ? Wp1 : Wp2);
    float*       C = (blockIdx.z == 0) ? Cp0 : ((blockIdx.z == 1) ? Cp1 : Cp2);

    __shared__ unsigned As[2][BM][BK/2 + 2];   // [m][kpair], stride 18 words
    __shared__ unsigned Bs[2][BK/2][BN + 8];   // [kpair][n], stride 72 words

    int tid  = threadIdx.x;
    int lane = tid & 31, warp = tid >> 5;
    int wm = (warp & 1) * 32;
    int wn = (warp >> 1) * 32;
    int row0 = blockIdx.y * BM, col0 = blockIdx.x * BN;
    int r = lane >> 2, cq = lane & 3;

    float acc[2][4][4];
    #pragma unroll
    for (int mi = 0; mi < 2; mi++)
        #pragma unroll
        for (int ni = 0; ni < 4; ni++)
            #pragma unroll
            for (int j = 0; j < 4; j++) acc[mi][ni][j] = 0.f;

    // A tile 64x32 floats: thread loads 4 float4 (rows arow+16i, k cols akc..akc+3)
    int arow = tid >> 3, akc = (tid & 7) << 2;
    // B tile 32x64 floats = 16 k-pairs x 64: thread handles pair-rows bpr, bpr+8, cols bnc..+3
    int bpr = tid >> 4, bnc = (tid & 15) << 2;

    const int NK = K / BK;
    float4 ar[4];            // A prefetch
    float4 bre[2], bro[2];   // B prefetch (even/odd k rows per pair-row)

    // prologue: load tile 0
    #pragma unroll
    for (int i = 0; i < 4; i++)
        ar[i] = *(const float4*)&A[(size_t)(row0 + arow + i*16)*K + akc];
    #pragma unroll
    for (int i = 0; i < 2; i++) {
        int pr = bpr + i*8;
        bre[i] = *(const float4*)&W[(size_t)(2*pr    )*Nd + col0 + bnc];
        bro[i] = *(const float4*)&W[(size_t)(2*pr + 1)*Nd + col0 + bnc];
    }
    #pragma unroll
    for (int i = 0; i < 4; i++) {
        uint2 ua = make_uint2(pack_bf16(ar[i].x, ar[i].y), pack_bf16(ar[i].z, ar[i].w));
        *(uint2*)&As[0][arow + i*16][akc >> 1] = ua;
    }
    #pragma unroll
    for (int i = 0; i < 2; i++) {
        uint4 ub = make_uint4(pack_bf16(bre[i].x, bro[i].x), pack_bf16(bre[i].y, bro[i].y),
                              pack_bf16(bre[i].z, bro[i].z), pack_bf16(bre[i].w, bro[i].w));
        *(uint4*)&Bs[0][bpr + i*8][bnc] = ub;
    }
    __syncthreads();

    for (int ki = 0; ki < NK; ki++) {
        int buf = ki & 1;
        if (ki + 1 < NK) {
            int k0 = (ki + 1) * BK;
            #pragma unroll
            for (int i = 0; i < 4; i++)
                ar[i] = *(const float4*)&A[(size_t)(row0 + arow + i*16)*K + k0 + akc];
            #pragma unroll
            for (int i = 0; i < 2; i++) {
                int pr = bpr + i*8;
                bre[i] = *(const float4*)&W[(size_t)(k0 + 2*pr    )*Nd + col0 + bnc];
                bro[i] = *(const float4*)&W[(size_t)(k0 + 2*pr + 1)*Nd + col0 + bnc];
            }
        }
        // compute: 2 k16-steps
        #pragma unroll
        for (int ks = 0; ks < 2; ks++) {
            int kb = ks * 8;
            unsigned af[2][4], bf[4][2];
            #pragma unroll
            for (int mi = 0; mi < 2; mi++) {
                int m = wm + mi*16 + r;
                af[mi][0] = As[buf][m    ][kb + cq];
                af[mi][1] = As[buf][m + 8][kb + cq];
                af[mi][2] = As[buf][m    ][kb + cq + 4];
                af[mi][3] = As[buf][m + 8][kb + cq + 4];
            }
            #pragma unroll
            for (int ni = 0; ni < 4; ni++) {
                int n = wn + ni*8 + r;
                bf[ni][0] = Bs[buf][kb + cq    ][n];
                bf[ni][1] = Bs[buf][kb + cq + 4][n];
            }
            #pragma unroll
            for (int mi = 0; mi < 2; mi++)
                #pragma unroll
                for (int ni = 0; ni < 4; ni++)
                    mma_bf16(acc[mi][ni], af[mi][0], af[mi][1], af[mi][2], af[mi][3],
                             bf[ni][0], bf[ni][1]);
        }
        if (ki + 1 < NK) {
            int nb = buf ^ 1;
            #pragma unroll
            for (int i = 0; i < 4; i++) {
                uint2 ua = make_uint2(pack_bf16(ar[i].x, ar[i].y), pack_bf16(ar[i].z, ar[i].w));
                *(uint2*)&As[nb][arow + i*16][akc >> 1] = ua;
            }
            #pragma unroll
            for (int i = 0; i < 2; i++) {
                uint4 ub = make_uint4(pack_bf16(bre[i].x, bro[i].x), pack_bf16(bre[i].y, bro[i].y),
                                      pack_bf16(bre[i].z, bro[i].z), pack_bf16(bre[i].w, bro[i].w));
                *(uint4*)&Bs[nb][bpr + i*8][bnc] = ub;
            }
            __syncthreads();
        }
    }

    // epilogue
    #pragma unroll
    for (int mi = 0; mi < 2; mi++) {
        #pragma unroll
        for (int ni = 0; ni < 4; ni++) {
            int row = row0 + wm + mi*16 + r;
            int col = col0 + wn + ni*8 + cq*2;
            #pragma unroll
            for (int half = 0; half < 2; half++) {
                int rr = row + half*8;
                float v0 = acc[mi][ni][half*2 + 0];
                float v1 = acc[mi][ni][half*2 + 1];
                if (bias) { v0 += bias[col]; v1 += bias[col + 1]; }
                if (res)  {
                    float2 rv = *(const float2*)&res[(size_t)rr*Nd + col];
                    v0 += rv.x; v1 += rv.y;
                }
                if (relu) { v0 = fmaxf(v0, 0.f); v1 = fmaxf(v1, 0.f); }
                float2 o = make_float2(v0, v1);
                *(float2*)&C[(size_t)rr*Nd + col] = o;
            }
        }
    }
}

// ---------------- MMA flash attention (tf32, no-max softmax) ----------------
#define KVP 36   // padded 32-bit stride per K/V/P row (conflict-free frag reads)

__global__ __launch_bounds__(256) void attn_kernel(
    const float* __restrict__ q, const float* __restrict__ k,
    const float* __restrict__ v, float* __restrict__ z)
{
    extern __shared__ unsigned sh[];
    unsigned* Ks = sh;                   // [256][KVP]
    unsigned* Vs = sh + 256*KVP;         // [256][KVP]
    unsigned* Ps = sh + 2*256*KVP;       // [8][16][KVP]

    int b = blockIdx.x, h = blockIdx.y, half = blockIdx.z;
    int tid = threadIdx.x, lane = tid & 31, warp = tid >> 5;
    int base = b * SEQ;
    int rows = (half + 1) * 128;

    const float scale = 0.17677669529663687f;   // 1/sqrt(32)

    for (int idx = tid; idx < rows*8; idx += 256) {
        int row = idx >> 3, c = (idx & 7) * 4;
        size_t off = (size_t)(base + row)*DIM + h*DKH + c;
        float4 kk = *(const float4*)&k[off];
        float4 vv = *(const float4*)&v[off];
        *(uint4*)&Ks[row*KVP + c] = make_uint4(f2tf(kk.x), f2tf(kk.y), f2tf(kk.z), f2tf(kk.w));
        *(uint4*)&Vs[row*KVP + c] = make_uint4(f2tf(vv.x), f2tf(vv.y), f2tf(vv.z), f2tf(vv.w));
    }
    __syncthreads();

    int r = lane >> 2, cq = lane & 3;
    int q0 = half*128 + warp*16;
    unsigned* Pw = Ps + warp*16*KVP;

    unsigned qa[4][4];
    #pragma unroll
    for (int ks = 0; ks < 4; ks++) {
        int c0 = ks*8 + cq;
        qa[ks][0] = f2tf(q[(size_t)(base + q0 + r    )*DIM + h*DKH + c0    ] * scale);
        qa[ks][1] = f2tf(q[(size_t)(base + q0 + 8 + r)*DIM + h*DKH + c0    ] * scale);
        qa[ks][2] = f2tf(q[(size_t)(base + q0 + r    )*DIM + h*DKH + c0 + 4] * scale);
        qa[ks][3] = f2tf(q[(size_t)(base + q0 + 8 + r)*DIM + h*DKH + c0 + 4] * scale);
    }

    float oacc[4][4];
    #pragma unroll
    for (int ni = 0; ni < 4; ni++)
        #pragma unroll
        for (int j = 0; j < 4; j++) oacc[ni][j] = 0.f;
    float lsum0 = 0.f, lsum1 = 0.f;

    int ntiles = ((q0 + 15) >> 5) + 1;
    int row0 = q0 + r, row1 = q0 + 8 + r;

    for (int t = 0; t < ntiles; t++) {
        int j0 = t * 32;

        float s[4][4];
        #pragma unroll
        for (int ni = 0; ni < 4; ni++)
            #pragma unroll
            for (int j = 0; j < 4; j++) s[ni][j] = 0.f;
        #pragma unroll
        for (int ks = 0; ks < 4; ks++) {
            unsigned bf[4][2];
            #pragma unroll
            for (int ni = 0; ni < 4; ni++) {
                int krow = (j0 + ni*8 + r) * KVP + ks*8 + cq;
                bf[ni][0] = Ks[krow];
                bf[ni][1] = Ks[krow + 4];
            }
            #pragma unroll
            for (int ni = 0; ni < 4; ni++)
                mma_tf32(s[ni], qa[ks][0], qa[ks][1], qa[ks][2], qa[ks][3],
                         bf[ni][0], bf[ni][1]);
        }

        #pragma unroll
        for (int ni = 0; ni < 4; ni++) {
            int j = j0 + ni*8 + 2*cq;
            float p0 = (j     <= row0) ? __expf(s[ni][0]) : 0.f;
            float p1 = (j + 1 <= row0) ? __expf(s[ni][1]) : 0.f;
            float p2 = (j     <= row1) ? __expf(s[ni][2]) : 0.f;
            float p3 = (j + 1 <= row1) ? __expf(s[ni][3]) : 0.f;
            unsigned u0 = f2tf(p0), u1 = f2tf(p1), u2 = f2tf(p2), u3 = f2tf(p3);
            lsum0 += __uint_as_float(u0) + __uint_as_float(u1);
            lsum1 += __uint_as_float(u2) + __uint_as_float(u3);
            *(uint2*)&Pw[ r      *KVP + ni*8 + 2*cq] = make_uint2(u0, u1);
            *(uint2*)&Pw[(r + 8)*KVP + ni*8 + 2*cq] = make_uint2(u2, u3);
        }
        __syncwarp();

        #pragma unroll
        for (int ks = 0; ks < 4; ks++) {
            unsigned pa0 = Pw[ r      *KVP + ks*8 + cq    ];
            unsigned pa1 = Pw[(r + 8)*KVP + ks*8 + cq    ];
            unsigned pa2 = Pw[ r      *KVP + ks*8 + cq + 4];
            unsigned pa3 = Pw[(r + 8)*KVP + ks*8 + cq + 4];
            #pragma unroll
            for (int ni = 0; ni < 4; ni++) {
                unsigned b0 = Vs[(j0 + ks*8 + cq    )*KVP + ni*8 + r];
                unsigned b1 = Vs[(j0 + ks*8 + cq + 4)*KVP + ni*8 + r];
                mma_tf32(oacc[ni], pa0, pa1, pa2, pa3, b0, b1);
            }
        }
        __syncwarp();
    }

    float l0 = lsum0, l1 = lsum1;
    l0 += __shfl_xor_sync(0xffffffffu, l0, 1);
    l0 += __shfl_xor_sync(0xffffffffu, l0, 2);
    l1 += __shfl_xor_sync(0xffffffffu, l1, 1);
    l1 += __shfl_xor_sync(0xffffffffu, l1, 2);
    float inv0 = 1.0f / l0, inv1 = 1.0f / l1;

    #pragma unroll
    for (int ni = 0; ni < 4; ni++) {
        int col = h*DKH + ni*8 + 2*cq;
        float2 o0 = make_float2(oacc[ni][0]*inv0, oacc[ni][1]*inv0);
        float2 o1 = make_float2(oacc[ni][2]*inv1, oacc[ni][3]*inv1);
        *(float2*)&z[(size_t)(base + q0 + r    )*DIM + col] = o0;
        *(float2*)&z[(size_t)(base + q0 + 8 + r)*DIM + col] = o1;
    }
}

// ---------------- log_softmax in-place on [NTOK, VOCAB] ----------------
__global__ void logsoftmax_kernel(float* __restrict__ out)
{
    int row = blockIdx.x;
    float* p = out + (size_t)row*VOCAB;
    int tid = threadIdx.x; // 256
    __shared__ float red[8];
    __shared__ float s_m, s_l;

    float m = -1e30f;
    for (int c = tid; c < VOCAB; c += 256) m = fmaxf(m, p[c]);
    #pragma unroll
    for (int o = 16; o; o >>= 1) m = fmaxf(m, __shfl_xor_sync(0xffffffffu, m, o));
    if ((tid & 31) == 0) red[tid >> 5] = m;
    __syncthreads();
    if (tid == 0) {
        float mm = red[0];
        #pragma unroll
        for (int i = 1; i < 8; i++) mm = fmaxf(mm, red[i]);
        s_m = mm;
    }
    __syncthreads();
    m = s_m;

    float s = 0.f;
    for (int c = tid; c < VOCAB; c += 256) s += expf(p[c] - m);
    #pragma unroll
    for (int o = 16; o; o >>= 1) s += __shfl_xor_sync(0xffffffffu, s, o);
    if ((tid & 31) == 0) red[tid >> 5] = s;
    __syncthreads();
    if (tid == 0) {
        float S = 0.f;
        #pragma unroll
        for (int i = 0; i < 8; i++) S += red[i];
        s_l = logf(S);
    }
    __syncthreads();
    float L = s_l;
    for (int c = tid; c < VOCAB; c += 256) p[c] = p[c] - m - L;
}

// ---------------- launcher ----------------
extern "C" void kernel_launch(void* const* d_in, const int* in_sizes, int n_in,
                              void* d_out, int out_size)
{
    const int*   tokens    = (const int*)  d_in[0];
    const int*   positions = (const int*)  d_in[1];
    const float* value_tab = (const float*)d_in[4];
    const float* coord_tab = (const float*)d_in[5];
    const float* pos_tab   = (const float*)d_in[6];
    const float* ln1_g     = (const float*)d_in[7];
    const float* ln1_b     = (const float*)d_in[8];
    const float* Wq        = (const float*)d_in[9];
    const float* Wk        = (const float*)d_in[10];
    const float* Wv        = (const float*)d_in[11];
    const float* Wo        = (const float*)d_in[12];
    const float* ln2_g     = (const float*)d_in[13];
    const float* ln2_b     = (const float*)d_in[14];
    const float* W1        = (const float*)d_in[15];
    const float* b1        = (const float*)d_in[16];
    const float* W2        = (const float*)d_in[17];
    const float* b2        = (const float*)d_in[18];
    const float* lnf_g     = (const float*)d_in[19];
    const float* lnf_b     = (const float*)d_in[20];
    const float* Wgen      = (const float*)d_in[21];
    const float* bgen      = (const float*)d_in[22];
    float* out = (float*)d_out;

    float *x, *xn, *q, *k, *v, *z, *ff;
    cudaGetSymbolAddress((void**)&x,  g_x);
    cudaGetSymbolAddress((void**)&xn, g_xn);
    cudaGetSymbolAddress((void**)&q,  g_q);
    cudaGetSymbolAddress((void**)&k,  g_k);
    cudaGetSymbolAddress((void**)&v,  g_v);
    cudaGetSymbolAddress((void**)&z,  g_z);
    cudaGetSymbolAddress((void**)&ff, g_ff);

    const int ATTN_SMEM = (2*256*KVP + 8*16*KVP) * 4;   // 92160 bytes
    cudaFuncSetAttribute(attn_kernel, cudaFuncAttributeMaxDynamicSharedMemorySize, ATTN_SMEM);

    embed_kernel<<<NTOK, DIM>>>(tokens, positions, value_tab, coord_tab, pos_tab, x);

    dim3 gD(DIM/BN,   NTOK/BM, 1);
    dim3 gQKV(DIM/BN, NTOK/BM, 3);
    dim3 gF(FFD/BN,   NTOK/BM, 1);
    dim3 gV(VOCAB/BN, NTOK/BM, 1);

    for (int i = 0; i < LAYERS; i++) {
        ln_kernel<<<NTOK, DIM>>>(x, ln1_g + i*DIM, ln1_b + i*DIM, xn);
        gemm_bf16<<<gQKV, 128>>>(xn,
                                 Wq + (size_t)i*DIM*DIM, Wk + (size_t)i*DIM*DIM, Wv + (size_t)i*DIM*DIM,
                                 nullptr, nullptr, q, k, v, NTOK, DIM, DIM, 0);
        attn_kernel<<<dim3(BATCH, HEADS, 2), 256, ATTN_SMEM>>>(q, k, v, z);
        gemm_bf16<<<gD, 128>>>(z, Wo + (size_t)i*DIM*DIM, nullptr, nullptr,
                               nullptr, x, x, nullptr, nullptr, NTOK, DIM, DIM, 0);
        ln_kernel<<<NTOK, DIM>>>(x, ln2_g + i*DIM, ln2_b + i*DIM, xn);
        gemm_bf16<<<gF, 128>>>(xn, W1 + (size_t)i*DIM*FFD, nullptr, nullptr,
                               b1 + i*FFD, nullptr, ff, nullptr, nullptr, NTOK, DIM, FFD, 1);
        gemm_bf16<<<gD, 128>>>(ff, W2 + (size_t)i*FFD*DIM, nullptr, nullptr,
                               b2 + i*DIM, x, x, nullptr, nullptr, NTOK, FFD, DIM, 0);
    }

    ln_kernel<<<NTOK, DIM>>>(x, lnf_g, lnf_b, xn);
    gemm_bf16<<<gV, 128>>>(xn, Wgen, nullptr, nullptr,
                           bgen, nullptr, out, nullptr, nullptr, NTOK, DIM, VOCAB, 0);
    logsoftmax_kernel<<<NTOK, 256>>>(out);
}

// round 6
// speedup vs baseline: 4.1769x; 1.3301x over previous
#include <cuda_runtime.h>
#include <cuda_bf16.h>
#include <math.h>

#define BATCH 8
#define SEQ 256
#define DIM 256
#define HEADS 8
#define DKH 32
#define LAYERS 4
#define VOCAB 2048
#define FFD 1024
#define NTOK (BATCH*SEQ)

// ---------------- scratch (allocation-free: __device__ globals) ----------------
__device__ float g_x [NTOK*DIM];
__device__ __nv_bfloat16 g_xn[NTOK*DIM];
__device__ float g_q [NTOK*DIM];
__device__ float g_k [NTOK*DIM];
__device__ float g_v [NTOK*DIM];
__device__ __nv_bfloat16 g_z [NTOK*DIM];
__device__ __nv_bfloat16 g_ff[NTOK*FFD];
__device__ __nv_bfloat16 g_wb[3670016];   // bf16 weight arena

// arena offsets (elements)
#define OFF_WQ 0
#define OFF_WK 262144
#define OFF_WV 524288
#define OFF_WO 786432
#define OFF_W1 1048576
#define OFF_W2 2097152
#define OFF_WG 3145728

// ---------------- helpers ----------------
__device__ __forceinline__ unsigned f2tf(float f) {
    unsigned u;
    asm("cvt.rna.tf32.f32 %0, %1;" : "=r"(u) : "f"(f));
    return u;
}
__device__ __forceinline__ unsigned pack_bf16(float lo, float hi) {
    unsigned u;
    asm("cvt.rn.bf16x2.f32 %0, %1, %2;" : "=r"(u) : "f"(hi), "f"(lo));
    return u;
}
__device__ __forceinline__ void mma_tf32(float c[4],
                                         unsigned a0, unsigned a1, unsigned a2, unsigned a3,
                                         unsigned b0, unsigned b1)
{
    asm volatile(
        "mma.sync.aligned.m16n8k8.row.col.f32.tf32.tf32.f32 "
        "{%0,%1,%2,%3}, {%4,%5,%6,%7}, {%8,%9}, {%0,%1,%2,%3};\n"
        : "+f"(c[0]), "+f"(c[1]), "+f"(c[2]), "+f"(c[3])
        : "r"(a0), "r"(a1), "r"(a2), "r"(a3), "r"(b0), "r"(b1));
}
__device__ __forceinline__ void mma_bf16(float c[4],
                                         unsigned a0, unsigned a1, unsigned a2, unsigned a3,
                                         unsigned b0, unsigned b1)
{
    asm volatile(
        "mma.sync.aligned.m16n8k16.row.col.f32.bf16.bf16.f32 "
        "{%0,%1,%2,%3}, {%4,%5,%6,%7}, {%8,%9}, {%0,%1,%2,%3};\n"
        : "+f"(c[0]), "+f"(c[1]), "+f"(c[2]), "+f"(c[3])
        : "r"(a0), "r"(a1), "r"(a2), "r"(a3), "r"(b0), "r"(b1));
}
__device__ __forceinline__ void ldsm_x4(unsigned r[4], unsigned addr) {
    asm volatile("ldmatrix.sync.aligned.m8n8.x4.shared.b16 {%0,%1,%2,%3}, [%4];"
                 : "=r"(r[0]), "=r"(r[1]), "=r"(r[2]), "=r"(r[3]) : "r"(addr));
}
__device__ __forceinline__ void ldsm_x4_t(unsigned r[4], unsigned addr) {
    asm volatile("ldmatrix.sync.aligned.m8n8.x4.trans.shared.b16 {%0,%1,%2,%3}, [%4];"
                 : "=r"(r[0]), "=r"(r[1]), "=r"(r[2]), "=r"(r[3]) : "r"(addr));
}
__device__ __forceinline__ void cp16(unsigned dst, const void* src) {
    asm volatile("cp.async.ca.shared.global [%0], [%1], 16;" :: "r"(dst), "l"(src));
}
#define CP_COMMIT() asm volatile("cp.async.commit_group;")
#define CP_WAIT1()  asm volatile("cp.async.wait_group 1;")

// ---------------- weight conversion fp32 -> bf16 arena ----------------
__global__ void convert_w(const float* __restrict__ s0, const float* __restrict__ s1,
                          const float* __restrict__ s2, const float* __restrict__ s3,
                          const float* __restrict__ s4, const float* __restrict__ s5,
                          const float* __restrict__ s6)
{
    const float* srcs[7] = {s0, s1, s2, s3, s4, s5, s6};
    const int counts[7]  = {262144, 262144, 262144, 262144, 1048576, 1048576, 524288};
    const int offs[7]    = {OFF_WQ, OFF_WK, OFF_WV, OFF_WO, OFF_W1, OFF_W2, OFF_WG};
    int seg = blockIdx.y;
    const float4* s = (const float4*)srcs[seg];
    uint2* d = (uint2*)(g_wb + offs[seg]);
    int n4 = counts[seg] >> 2;
    for (int i = blockIdx.x*blockDim.x + threadIdx.x; i < n4; i += gridDim.x*blockDim.x) {
        float4 v = s[i];
        d[i] = make_uint2(pack_bf16(v.x, v.y), pack_bf16(v.z, v.w));
    }
}

// ---------------- embedding ----------------
__global__ void embed_kernel(const int* __restrict__ tokens, const int* __restrict__ positions,
                             const float* __restrict__ value_tab, const float* __restrict__ coord_tab,
                             const float* __restrict__ pos_tab, float* __restrict__ x)
{
    int n = blockIdx.x, d = threadIdx.x;
    int t = tokens[n], p = positions[n];
    x[(size_t)n*DIM + d] = value_tab[(size_t)t*DIM + d] * 16.0f
                         + coord_tab[(p % 3)*DIM + d]
                         + pos_tab[(p / 3)*DIM + d];
}

// ---------------- layernorm (fp32 in -> bf16 out) ----------------
__global__ void ln_kernel(const float* __restrict__ x, const float* __restrict__ g,
                          const float* __restrict__ b, __nv_bfloat16* __restrict__ out)
{
    int row = blockIdx.x;
    int tid = threadIdx.x; // 256 == DIM
    float v = x[(size_t)row*DIM + tid];
    float s = v, sq = v*v;
    #pragma unroll
    for (int o = 16; o; o >>= 1) {
        s  += __shfl_xor_sync(0xffffffffu, s,  o);
        sq += __shfl_xor_sync(0xffffffffu, sq, o);
    }
    __shared__ float rs[8], rq[8];
    __shared__ float s_mean, s_rstd;
    if ((tid & 31) == 0) { rs[tid >> 5] = s; rq[tid >> 5] = sq; }
    __syncthreads();
    if (tid == 0) {
        float S = 0.f, Q = 0.f;
        #pragma unroll
        for (int i = 0; i < 8; i++) { S += rs[i]; Q += rq[i]; }
        float mean = S * (1.0f/DIM);
        float var  = Q * (1.0f/DIM) - mean*mean;
        s_mean = mean;
        s_rstd = rsqrtf(var + 1e-5f);
    }
    __syncthreads();
    out[(size_t)row*DIM + tid] = __float2bfloat16((v - s_mean) * s_rstd * g[tid] + b[tid]);
}

// ---------------- pipelined bf16 GEMM: cp.async + ldmatrix ----------------
// C = A[M,K](bf16) @ W[K,Nd](bf16) (+bias)(+res)(relu); fp32 accumulate.
// 64x64 CTA tile, BK=64, 3-stage cp.async pipeline, 128 threads = 4 warps
// (warp tile 32x32 = 2x4 m16n8k16). Smem rows 128B, XOR-swizzled (c ^= row&7).
#define GBK 64
#define STG 3

__global__ __launch_bounds__(128) void gemm_bf16(
    const __nv_bfloat16* __restrict__ A,
    const __nv_bfloat16* Wp0, const __nv_bfloat16* Wp1, const __nv_bfloat16* Wp2,
    const float* __restrict__ bias, const float* __restrict__ res,
    void* Cp0, void* Cp1, void* Cp2,
    int K, int Nd, int relu, int outbf)
{
    const __nv_bfloat16* W = (blockIdx.z == 0) ? Wp0 : ((blockIdx.z == 1) ? Wp1 : Wp2);
    void* C = (blockIdx.z == 0) ? Cp0 : ((blockIdx.z == 1) ? Cp1 : Cp2);

    extern __shared__ __nv_bfloat16 sm[];
    unsigned sa = (unsigned)__cvta_generic_to_shared(sm);            // A stages: 3*8192B
    unsigned sb = sa + STG*8192;                                     // B stages: 3*8192B

    int tid  = threadIdx.x;
    int lane = tid & 31, warp = tid >> 5;
    int wm = (warp & 1) * 32, wn = (warp >> 1) * 32;
    int row0 = blockIdx.y * 64, col0 = blockIdx.x * 64;

    float acc[2][4][4];
    #pragma unroll
    for (int mi = 0; mi < 2; mi++)
        #pragma unroll
        for (int ni = 0; ni < 4; ni++)
            #pragma unroll
            for (int j = 0; j < 4; j++) acc[mi][ni][j] = 0.f;

    const int NK = K / GBK;

    // ldmatrix lane addressing (within-stage offsets)
    int lrow = lane & 15, lsel = lane >> 4;

    // stage loader: 512 16B chunks each for A and B, 8 per thread
    auto stage_load = [&](int s, int k0) {
        unsigned ab = sa + s*8192, bb = sb + s*8192;
        #pragma unroll
        for (int i = 0; i < 4; i++) {
            int id = tid + i*128;
            int row = id >> 3, c = id & 7;
            cp16(ab + row*128 + (((c ^ (row & 7))) << 4),
                 &A[(size_t)(row0 + row)*K + k0 + c*8]);
        }
        #pragma unroll
        for (int i = 0; i < 4; i++) {
            int id = tid + i*128;
            int row = id >> 3, c = id & 7;
            cp16(bb + row*128 + (((c ^ (row & 7))) << 4),
                 &W[(size_t)(k0 + row)*Nd + col0 + c*8]);
        }
    };

    stage_load(0, 0);      CP_COMMIT();
    stage_load(1, GBK);    CP_COMMIT();

    for (int ki = 0; ki < NK; ki++) {
        CP_WAIT1();
        __syncthreads();
        int s = ki % STG;
        unsigned ab = sa + s*8192, bb = sb + s*8192;

        #pragma unroll
        for (int ks = 0; ks < 4; ks++) {
            int k0 = ks * 16;
            unsigned af[2][4], bfr[2][4];
            #pragma unroll
            for (int mi = 0; mi < 2; mi++) {
                int m = wm + mi*16 + lrow;
                int c = (k0 >> 3) + lsel;
                ldsm_x4(af[mi], ab + m*128 + ((c ^ (m & 7)) << 4));
            }
            #pragma unroll
            for (int bi = 0; bi < 2; bi++) {
                int kr = k0 + lrow;
                int c = ((wn + bi*16) >> 3) + lsel;
                ldsm_x4_t(bfr[bi], bb + kr*128 + ((c ^ (kr & 7)) << 4));
            }
            #pragma unroll
            for (int mi = 0; mi < 2; mi++) {
                mma_bf16(acc[mi][0], af[mi][0], af[mi][1], af[mi][2], af[mi][3], bfr[0][0], bfr[0][1]);
                mma_bf16(acc[mi][1], af[mi][0], af[mi][1], af[mi][2], af[mi][3], bfr[0][2], bfr[0][3]);
                mma_bf16(acc[mi][2], af[mi][0], af[mi][1], af[mi][2], af[mi][3], bfr[1][0], bfr[1][1]);
                mma_bf16(acc[mi][3], af[mi][0], af[mi][1], af[mi][2], af[mi][3], bfr[1][2], bfr[1][3]);
            }
        }

        int kn = ki + STG - 1;
        if (kn < NK) stage_load(kn % STG, kn*GBK);
        CP_COMMIT();
        __syncthreads();
    }

    // epilogue
    int r = lane >> 2, cq = lane & 3;
    #pragma unroll
    for (int mi = 0; mi < 2; mi++) {
        #pragma unroll
        for (int ni = 0; ni < 4; ni++) {
            int row = row0 + wm + mi*16 + r;
            int col = col0 + wn + ni*8 + cq*2;
            #pragma unroll
            for (int half = 0; half < 2; half++) {
                int rr = row + half*8;
                float v0 = acc[mi][ni][half*2 + 0];
                float v1 = acc[mi][ni][half*2 + 1];
                if (bias) { v0 += bias[col]; v1 += bias[col + 1]; }
                if (res)  {
                    float2 rv = *(const float2*)&res[(size_t)rr*Nd + col];
                    v0 += rv.x; v1 += rv.y;
                }
                if (relu) { v0 = fmaxf(v0, 0.f); v1 = fmaxf(v1, 0.f); }
                if (outbf) {
                    *(unsigned*)&((__nv_bfloat16*)C)[(size_t)rr*Nd + col] = pack_bf16(v0, v1);
                } else {
                    *(float2*)&((float*)C)[(size_t)rr*Nd + col] = make_float2(v0, v1);
                }
            }
        }
    }
}

// ---------------- MMA flash attention (tf32, no-max softmax); z out bf16 ----------------
#define KVP 36

__global__ __launch_bounds__(256) void attn_kernel(
    const float* __restrict__ q, const float* __restrict__ k,
    const float* __restrict__ v, __nv_bfloat16* __restrict__ z)
{
    extern __shared__ unsigned sh[];
    unsigned* Ks = sh;
    unsigned* Vs = sh + 256*KVP;
    unsigned* Ps = sh + 2*256*KVP;

    int b = blockIdx.x, h = blockIdx.y, half = blockIdx.z;
    int tid = threadIdx.x, lane = tid & 31, warp = tid >> 5;
    int base = b * SEQ;
    int rows = (half + 1) * 128;

    const float scale = 0.17677669529663687f;

    for (int idx = tid; idx < rows*8; idx += 256) {
        int row = idx >> 3, c = (idx & 7) * 4;
        size_t off = (size_t)(base + row)*DIM + h*DKH + c;
        float4 kk = *(const float4*)&k[off];
        float4 vv = *(const float4*)&v[off];
        *(uint4*)&Ks[row*KVP + c] = make_uint4(f2tf(kk.x), f2tf(kk.y), f2tf(kk.z), f2tf(kk.w));
        *(uint4*)&Vs[row*KVP + c] = make_uint4(f2tf(vv.x), f2tf(vv.y), f2tf(vv.z), f2tf(vv.w));
    }
    __syncthreads();

    int r = lane >> 2, cq = lane & 3;
    int q0 = half*128 + warp*16;
    unsigned* Pw = Ps + warp*16*KVP;

    unsigned qa[4][4];
    #pragma unroll
    for (int ks = 0; ks < 4; ks++) {
        int c0 = ks*8 + cq;
        qa[ks][0] = f2tf(q[(size_t)(base + q0 + r    )*DIM + h*DKH + c0    ] * scale);
        qa[ks][1] = f2tf(q[(size_t)(base + q0 + 8 + r)*DIM + h*DKH + c0    ] * scale);
        qa[ks][2] = f2tf(q[(size_t)(base + q0 + r    )*DIM + h*DKH + c0 + 4] * scale);
        qa[ks][3] = f2tf(q[(size_t)(base + q0 + 8 + r)*DIM + h*DKH + c0 + 4] * scale);
    }

    float oacc[4][4];
    #pragma unroll
    for (int ni = 0; ni < 4; ni++)
        #pragma unroll
        for (int j = 0; j < 4; j++) oacc[ni][j] = 0.f;
    float lsum0 = 0.f, lsum1 = 0.f;

    int ntiles = ((q0 + 15) >> 5) + 1;
    int row0 = q0 + r, row1 = q0 + 8 + r;

    for (int t = 0; t < ntiles; t++) {
        int j0 = t * 32;

        float s[4][4];
        #pragma unroll
        for (int ni = 0; ni < 4; ni++)
            #pragma unroll
            for (int j = 0; j < 4; j++) s[ni][j] = 0.f;
        #pragma unroll
        for (int ks = 0; ks < 4; ks++) {
            unsigned bf[4][2];
            #pragma unroll
            for (int ni = 0; ni < 4; ni++) {
                int krow = (j0 + ni*8 + r) * KVP + ks*8 + cq;
                bf[ni][0] = Ks[krow];
                bf[ni][1] = Ks[krow + 4];
            }
            #pragma unroll
            for (int ni = 0; ni < 4; ni++)
                mma_tf32(s[ni], qa[ks][0], qa[ks][1], qa[ks][2], qa[ks][3],
                         bf[ni][0], bf[ni][1]);
        }

        #pragma unroll
        for (int ni = 0; ni < 4; ni++) {
            int j = j0 + ni*8 + 2*cq;
            float p0 = (j     <= row0) ? __expf(s[ni][0]) : 0.f;
            float p1 = (j + 1 <= row0) ? __expf(s[ni][1]) : 0.f;
            float p2 = (j     <= row1) ? __expf(s[ni][2]) : 0.f;
            float p3 = (j + 1 <= row1) ? __expf(s[ni][3]) : 0.f;
            unsigned u0 = f2tf(p0), u1 = f2tf(p1), u2 = f2tf(p2), u3 = f2tf(p3);
            lsum0 += __uint_as_float(u0) + __uint_as_float(u1);
            lsum1 += __uint_as_float(u2) + __uint_as_float(u3);
            *(uint2*)&Pw[ r      *KVP + ni*8 + 2*cq] = make_uint2(u0, u1);
            *(uint2*)&Pw[(r + 8)*KVP + ni*8 + 2*cq] = make_uint2(u2, u3);
        }
        __syncwarp();

        #pragma unroll
        for (int ks = 0; ks < 4; ks++) {
            unsigned pa0 = Pw[ r      *KVP + ks*8 + cq    ];
            unsigned pa1 = Pw[(r + 8)*KVP + ks*8 + cq    ];
            unsigned pa2 = Pw[ r      *KVP + ks*8 + cq + 4];
            unsigned pa3 = Pw[(r + 8)*KVP + ks*8 + cq + 4];
            #pragma unroll
            for (int ni = 0; ni < 4; ni++) {
                unsigned b0 = Vs[(j0 + ks*8 + cq    )*KVP + ni*8 + r];
                unsigned b1 = Vs[(j0 + ks*8 + cq + 4)*KVP + ni*8 + r];
                mma_tf32(oacc[ni], pa0, pa1, pa2, pa3, b0, b1);
            }
        }
        __syncwarp();
    }

    float l0 = lsum0, l1 = lsum1;
    l0 += __shfl_xor_sync(0xffffffffu, l0, 1);
    l0 += __shfl_xor_sync(0xffffffffu, l0, 2);
    l1 += __shfl_xor_sync(0xffffffffu, l1, 1);
    l1 += __shfl_xor_sync(0xffffffffu, l1, 2);
    float inv0 = 1.0f / l0, inv1 = 1.0f / l1;

    #pragma unroll
    for (int ni = 0; ni < 4; ni++) {
        int col = h*DKH + ni*8 + 2*cq;
        *(unsigned*)&z[(size_t)(base + q0 + r    )*DIM + col] =
            pack_bf16(oacc[ni][0]*inv0, oacc[ni][1]*inv0);
        *(unsigned*)&z[(size_t)(base + q0 + 8 + r)*DIM + col] =
            pack_bf16(oacc[ni][2]*inv1, oacc[ni][3]*inv1);
    }
}

// ---------------- log_softmax in-place on [NTOK, VOCAB] ----------------
__global__ void logsoftmax_kernel(float* __restrict__ out)
{
    int row = blockIdx.x;
    float* p = out + (size_t)row*VOCAB;
    int tid = threadIdx.x; // 256
    __shared__ float red[8];
    __shared__ float s_m, s_l;

    float m = -1e30f;
    for (int c = tid; c < VOCAB; c += 256) m = fmaxf(m, p[c]);
    #pragma unroll
    for (int o = 16; o; o >>= 1) m = fmaxf(m, __shfl_xor_sync(0xffffffffu, m, o));
    if ((tid & 31) == 0) red[tid >> 5] = m;
    __syncthreads();
    if (tid == 0) {
        float mm = red[0];
        #pragma unroll
        for (int i = 1; i < 8; i++) mm = fmaxf(mm, red[i]);
        s_m = mm;
    }
    __syncthreads();
    m = s_m;

    float s = 0.f;
    for (int c = tid; c < VOCAB; c += 256) s += expf(p[c] - m);
    #pragma unroll
    for (int o = 16; o; o >>= 1) s += __shfl_xor_sync(0xffffffffu, s, o);
    if ((tid & 31) == 0) red[tid >> 5] = s;
    __syncthreads();
    if (tid == 0) {
        float S = 0.f;
        #pragma unroll
        for (int i = 0; i < 8; i++) S += red[i];
        s_l = logf(S);
    }
    __syncthreads();
    float L = s_l;
    for (int c = tid; c < VOCAB; c += 256) p[c] = p[c] - m - L;
}

// ---------------- launcher ----------------
extern "C" void kernel_launch(void* const* d_in, const int* in_sizes, int n_in,
                              void* d_out, int out_size)
{
    const int*   tokens    = (const int*)  d_in[0];
    const int*   positions = (const int*)  d_in[1];
    const float* value_tab = (const float*)d_in[4];
    const float* coord_tab = (const float*)d_in[5];
    const float* pos_tab   = (const float*)d_in[6];
    const float* ln1_g     = (const float*)d_in[7];
    const float* ln1_b     = (const float*)d_in[8];
    const float* Wq        = (const float*)d_in[9];
    const float* Wk        = (const float*)d_in[10];
    const float* Wv        = (const float*)d_in[11];
    const float* Wo        = (const float*)d_in[12];
    const float* ln2_g     = (const float*)d_in[13];
    const float* ln2_b     = (const float*)d_in[14];
    const float* W1        = (const float*)d_in[15];
    const float* b1        = (const float*)d_in[16];
    const float* W2        = (const float*)d_in[17];
    const float* b2        = (const float*)d_in[18];
    const float* lnf_g     = (const float*)d_in[19];
    const float* lnf_b     = (const float*)d_in[20];
    const float* Wgen      = (const float*)d_in[21];
    const float* bgen      = (const float*)d_in[22];
    float* out = (float*)d_out;

    float *x, *q, *k, *v;
    __nv_bfloat16 *xn, *z, *ff, *wb;
    cudaGetSymbolAddress((void**)&x,  g_x);
    cudaGetSymbolAddress((void**)&xn, g_xn);
    cudaGetSymbolAddress((void**)&q,  g_q);
    cudaGetSymbolAddress((void**)&k,  g_k);
    cudaGetSymbolAddress((void**)&v,  g_v);
    cudaGetSymbolAddress((void**)&z,  g_z);
    cudaGetSymbolAddress((void**)&ff, g_ff);
    cudaGetSymbolAddress((void**)&wb, g_wb);

    const int ATTN_SMEM = (2*256*KVP + 8*16*KVP) * 4;   // 92160 bytes
    const int GEMM_SMEM = STG * 8192 * 2;               // 49152 bytes
    cudaFuncSetAttribute(attn_kernel, cudaFuncAttributeMaxDynamicSharedMemorySize, ATTN_SMEM);
    cudaFuncSetAttribute(gemm_bf16,   cudaFuncAttributeMaxDynamicSharedMemorySize, GEMM_SMEM);

    convert_w<<<dim3(256, 7), 256>>>(Wq, Wk, Wv, Wo, W1, W2, Wgen);
    embed_kernel<<<NTOK, DIM>>>(tokens, positions, value_tab, coord_tab, pos_tab, x);

    dim3 gD(DIM/64,   NTOK/64, 1);
    dim3 gQKV(DIM/64, NTOK/64, 3);
    dim3 gF(FFD/64,   NTOK/64, 1);
    dim3 gV(VOCAB/64, NTOK/64, 1);

    for (int i = 0; i < LAYERS; i++) {
        ln_kernel<<<NTOK, DIM>>>(x, ln1_g + i*DIM, ln1_b + i*DIM, xn);
        gemm_bf16<<<gQKV, 128, GEMM_SMEM>>>(xn,
                                 wb + OFF_WQ + i*DIM*DIM, wb + OFF_WK + i*DIM*DIM, wb + OFF_WV + i*DIM*DIM,
                                 nullptr, nullptr, q, k, v, DIM, DIM, 0, 0);
        attn_kernel<<<dim3(BATCH, HEADS, 2), 256, ATTN_SMEM>>>(q, k, v, z);
        gemm_bf16<<<gD, 128, GEMM_SMEM>>>(z, wb + OFF_WO + i*DIM*DIM, nullptr, nullptr,
                               nullptr, x, x, nullptr, nullptr, DIM, DIM, 0, 0);
        ln_kernel<<<NTOK, DIM>>>(x, ln2_g + i*DIM, ln2_b + i*DIM, xn);
        gemm_bf16<<<gF, 128, GEMM_SMEM>>>(xn, wb + OFF_W1 + i*DIM*FFD, nullptr, nullptr,
                               b1 + i*FFD, nullptr, ff, nullptr, nullptr, DIM, FFD, 1, 1);
        gemm_bf16<<<gD, 128, GEMM_SMEM>>>(ff, wb + OFF_W2 + i*FFD*DIM, nullptr, nullptr,
                               b2 + i*DIM, x, x, nullptr, nullptr, FFD, DIM, 0, 0);
    }

    ln_kernel<<<NTOK, DIM>>>(x, lnf_g, lnf_b, xn);
    gemm_bf16<<<gV, 128, GEMM_SMEM>>>(xn, wb + OFF_WG, nullptr, nullptr,
                           bgen, nullptr, out, nullptr, nullptr, DIM, VOCAB, 0, 0);
    logsoftmax_kernel<<<NTOK, 256>>>(out);
}